// round 1
// baseline (speedup 1.0000x reference)
#include <cuda_runtime.h>
#include <cuda_bf16.h>

// EdgeDecoder: probs = sigmoid(relu(relu(concat(emb[u],emb[v]) @ W1 + b1) @ W2 + b2) @ W3 + b3)
// Trick: concat @ W1 = emb[u] @ W1[:16] + emb[v] @ W1[16:]  -> precompute per-node partials.

#define MAX_NODES 100000
#define HID 64

// Per-node precomputed partials: Pa = emb @ W1[0:16] + b1, Pb = emb @ W1[16:32]
__device__ float g_Pa[(size_t)MAX_NODES * HID];
__device__ float g_Pb[(size_t)MAX_NODES * HID];

__global__ void __launch_bounds__(256)
precompute_kernel(const float* __restrict__ emb,
                  const float* __restrict__ W1,
                  const float* __restrict__ b1,
                  int n_nodes) {
    __shared__ float sW1[32 * 64];
    __shared__ float sb1[64];
    for (int i = threadIdx.x; i < 32 * 64; i += blockDim.x) sW1[i] = W1[i];
    if (threadIdx.x < 64) sb1[threadIdx.x] = b1[threadIdx.x];
    __syncthreads();

    int n = blockIdx.x * blockDim.x + threadIdx.x;
    if (n >= n_nodes) return;

    float x[16];
    const float4* e4 = (const float4*)(emb + (size_t)n * 16);
#pragma unroll
    for (int i = 0; i < 4; i++) {
        float4 t = e4[i];
        x[4 * i + 0] = t.x; x[4 * i + 1] = t.y;
        x[4 * i + 2] = t.z; x[4 * i + 3] = t.w;
    }

    float acc[64];
#pragma unroll
    for (int j = 0; j < 64; j++) acc[j] = sb1[j];
#pragma unroll
    for (int k = 0; k < 16; k++)
#pragma unroll
        for (int j = 0; j < 64; j++)
            acc[j] = fmaf(x[k], sW1[k * 64 + j], acc[j]);
    {
        float4* pa = (float4*)(g_Pa + (size_t)n * 64);
#pragma unroll
        for (int j4 = 0; j4 < 16; j4++)
            pa[j4] = make_float4(acc[4 * j4], acc[4 * j4 + 1], acc[4 * j4 + 2], acc[4 * j4 + 3]);
    }

#pragma unroll
    for (int j = 0; j < 64; j++) acc[j] = 0.0f;
#pragma unroll
    for (int k = 0; k < 16; k++)
#pragma unroll
        for (int j = 0; j < 64; j++)
            acc[j] = fmaf(x[k], sW1[(16 + k) * 64 + j], acc[j]);
    {
        float4* pb = (float4*)(g_Pb + (size_t)n * 64);
#pragma unroll
        for (int j4 = 0; j4 < 16; j4++)
            pb[j4] = make_float4(acc[4 * j4], acc[4 * j4 + 1], acc[4 * j4 + 2], acc[4 * j4 + 3]);
    }
}

__global__ void __launch_bounds__(256)
edge_kernel(const int* __restrict__ ei,
            const float* __restrict__ W2,
            const float* __restrict__ b2,
            const float* __restrict__ W3,
            const float* __restrict__ b3,
            float* __restrict__ out,
            int E) {
    __shared__ float sW2[64 * 32];     // row-major [k][j]
    __shared__ float sW3[32];
    __shared__ float sb2[32];
    __shared__ float sb3;
    for (int i = threadIdx.x; i < 64 * 32; i += blockDim.x) sW2[i] = W2[i];
    if (threadIdx.x < 32) { sW3[threadIdx.x] = W3[threadIdx.x]; sb2[threadIdx.x] = b2[threadIdx.x]; }
    if (threadIdx.x == 0) sb3 = b3[0];
    __syncthreads();

    int e = blockIdx.x * blockDim.x + threadIdx.x;
    if (e >= E) return;

    int u = __ldg(ei + e);
    int v = __ldg(ei + (size_t)E + e);

    const float4* pa = (const float4*)(g_Pa + (size_t)u * 64);
    const float4* pb = (const float4*)(g_Pb + (size_t)v * 64);

    float h2[32];
#pragma unroll
    for (int j = 0; j < 32; j++) h2[j] = sb2[j];

#pragma unroll
    for (int kk = 0; kk < 16; kk++) {
        float4 a = pa[kk];
        float4 b = pb[kk];
        float h0 = fmaxf(a.x + b.x, 0.0f);
        float h1 = fmaxf(a.y + b.y, 0.0f);
        float hc = fmaxf(a.z + b.z, 0.0f);
        float h3 = fmaxf(a.w + b.w, 0.0f);
        const float4* w0 = (const float4*)(sW2 + (4 * kk + 0) * 32);
        const float4* w1 = (const float4*)(sW2 + (4 * kk + 1) * 32);
        const float4* w2 = (const float4*)(sW2 + (4 * kk + 2) * 32);
        const float4* w3 = (const float4*)(sW2 + (4 * kk + 3) * 32);
#pragma unroll
        for (int j4 = 0; j4 < 8; j4++) {
            float4 wa = w0[j4], wb = w1[j4], wc = w2[j4], wd = w3[j4];
            h2[4 * j4 + 0] = fmaf(h0, wa.x, fmaf(h1, wb.x, fmaf(hc, wc.x, fmaf(h3, wd.x, h2[4 * j4 + 0]))));
            h2[4 * j4 + 1] = fmaf(h0, wa.y, fmaf(h1, wb.y, fmaf(hc, wc.y, fmaf(h3, wd.y, h2[4 * j4 + 1]))));
            h2[4 * j4 + 2] = fmaf(h0, wa.z, fmaf(h1, wb.z, fmaf(hc, wc.z, fmaf(h3, wd.z, h2[4 * j4 + 2]))));
            h2[4 * j4 + 3] = fmaf(h0, wa.w, fmaf(h1, wb.w, fmaf(hc, wc.w, fmaf(h3, wd.w, h2[4 * j4 + 3]))));
        }
    }

    float z = sb3;
#pragma unroll
    for (int j = 0; j < 32; j++)
        z = fmaf(fmaxf(h2[j], 0.0f), sW3[j], z);

    out[e] = 1.0f / (1.0f + __expf(-z));
}

__global__ void __launch_bounds__(256)
idx_copy_kernel(const int* __restrict__ ei, float* __restrict__ out, int n) {
    int i = blockIdx.x * blockDim.x + threadIdx.x;
    if (i < n) out[i] = (float)ei[i];
}

extern "C" void kernel_launch(void* const* d_in, const int* in_sizes, int n_in,
                              void* d_out, int out_size) {
    const float* emb = (const float*)d_in[0];
    const int*   ei  = (const int*)d_in[1];
    const float* W1  = (const float*)d_in[2];
    const float* b1  = (const float*)d_in[3];
    const float* W2  = (const float*)d_in[4];
    const float* b2  = (const float*)d_in[5];
    const float* W3  = (const float*)d_in[6];
    const float* b3  = (const float*)d_in[7];

    int n_nodes = in_sizes[0] / 16;
    int E       = in_sizes[1] / 2;
    float* out  = (float*)d_out;

    precompute_kernel<<<(n_nodes + 255) / 256, 256>>>(emb, W1, b1, n_nodes);
    edge_kernel<<<(E + 255) / 256, 256>>>(ei, W2, b2, W3, b3, out, E);

    // Reference also returns edge_index; if the flattened output includes it,
    // append it (cast to float is exact for node ids < 2^24).
    if (out_size >= 3 * E) {
        int n = 2 * E;
        idx_copy_kernel<<<(n + 255) / 256, 256>>>(ei, out + E, n);
    }
}

// round 2
// speedup vs baseline: 1.2416x; 1.2416x over previous
#include <cuda_runtime.h>
#include <cuda_bf16.h>

// EdgeDecoder: probs = sigmoid(relu(relu(concat(emb[u],emb[v]) @ W1 + b1) @ W2 + b2) @ W3 + b3)
// R1: concat@W1 factored into per-node partials Pa/Pb (precompute).
// R2: layer2 inner product via packed fma.rn.f32x2 (2 fp32 FMA per instr, Blackwell),
//     2 edges per thread to amortize W2 shared-memory loads (LDS was co-binding).

#define MAX_NODES 100000
#define HID 64

__device__ float g_Pa[(size_t)MAX_NODES * HID];
__device__ float g_Pb[(size_t)MAX_NODES * HID];

// ---- packed f32x2 helpers (sm_100+) ----
__device__ __forceinline__ unsigned long long fma2(unsigned long long a,
                                                   unsigned long long b,
                                                   unsigned long long c) {
    unsigned long long d;
    asm("fma.rn.f32x2 %0, %1, %2, %3;" : "=l"(d) : "l"(a), "l"(b), "l"(c));
    return d;
}
__device__ __forceinline__ unsigned long long pack2(float x) {
    unsigned long long r;
    asm("mov.b64 %0, {%1, %1};" : "=l"(r) : "f"(x));
    return r;
}
__device__ __forceinline__ void unpack2(unsigned long long v, float& lo, float& hi) {
    asm("mov.b64 {%0, %1}, %2;" : "=f"(lo), "=f"(hi) : "l"(v));
}

__global__ void __launch_bounds__(256)
precompute_kernel(const float* __restrict__ emb,
                  const float* __restrict__ W1,
                  const float* __restrict__ b1,
                  int n_nodes) {
    __shared__ float sW1[32 * 64];
    __shared__ float sb1[64];
    for (int i = threadIdx.x; i < 32 * 64; i += blockDim.x) sW1[i] = W1[i];
    if (threadIdx.x < 64) sb1[threadIdx.x] = b1[threadIdx.x];
    __syncthreads();

    int n = blockIdx.x * blockDim.x + threadIdx.x;
    if (n >= n_nodes) return;

    float x[16];
    const float4* e4 = (const float4*)(emb + (size_t)n * 16);
#pragma unroll
    for (int i = 0; i < 4; i++) {
        float4 t = e4[i];
        x[4 * i + 0] = t.x; x[4 * i + 1] = t.y;
        x[4 * i + 2] = t.z; x[4 * i + 3] = t.w;
    }

    float acc[64];
#pragma unroll
    for (int j = 0; j < 64; j++) acc[j] = sb1[j];
#pragma unroll
    for (int k = 0; k < 16; k++)
#pragma unroll
        for (int j = 0; j < 64; j++)
            acc[j] = fmaf(x[k], sW1[k * 64 + j], acc[j]);
    {
        float4* pa = (float4*)(g_Pa + (size_t)n * 64);
#pragma unroll
        for (int j4 = 0; j4 < 16; j4++)
            pa[j4] = make_float4(acc[4 * j4], acc[4 * j4 + 1], acc[4 * j4 + 2], acc[4 * j4 + 3]);
    }

#pragma unroll
    for (int j = 0; j < 64; j++) acc[j] = 0.0f;
#pragma unroll
    for (int k = 0; k < 16; k++)
#pragma unroll
        for (int j = 0; j < 64; j++)
            acc[j] = fmaf(x[k], sW1[(16 + k) * 64 + j], acc[j]);
    {
        float4* pb = (float4*)(g_Pb + (size_t)n * 64);
#pragma unroll
        for (int j4 = 0; j4 < 16; j4++)
            pb[j4] = make_float4(acc[4 * j4], acc[4 * j4 + 1], acc[4 * j4 + 2], acc[4 * j4 + 3]);
    }
}

// Each thread processes 2 edges: e0 = tid (first half) and e1 = tid + H (second half).
__global__ void __launch_bounds__(256)
edge_kernel(const int* __restrict__ ei,
            const float* __restrict__ W2,
            const float* __restrict__ b2,
            const float* __restrict__ W3,
            const float* __restrict__ b3,
            float* __restrict__ out,
            int E, int H) {
    __shared__ float sW2[64 * 32];     // row-major [k][j]
    __shared__ float sW3[32];
    __shared__ float sb2[32];
    __shared__ float sb3;
    for (int i = threadIdx.x; i < 64 * 32; i += blockDim.x) sW2[i] = W2[i];
    if (threadIdx.x < 32) { sW3[threadIdx.x] = W3[threadIdx.x]; sb2[threadIdx.x] = b2[threadIdx.x]; }
    if (threadIdx.x == 0) sb3 = b3[0];
    __syncthreads();

    int tid = blockIdx.x * blockDim.x + threadIdx.x;
    int e0 = tid;
    int e1 = tid + H;
    bool do0 = (e0 < E) && (e0 < H);
    bool do1 = (e1 < E);
    if (!do0 && !do1) return;

    int u0 = 0, v0 = 0, u1 = 0, v1 = 0;
    if (do0) { u0 = __ldg(ei + e0); v0 = __ldg(ei + (size_t)E + e0); }
    if (do1) { u1 = __ldg(ei + e1); v1 = __ldg(ei + (size_t)E + e1); }

    const float4* pa0 = (const float4*)(g_Pa + (size_t)u0 * 64);
    const float4* pb0 = (const float4*)(g_Pb + (size_t)v0 * 64);
    const float4* pa1 = (const float4*)(g_Pa + (size_t)u1 * 64);
    const float4* pb1 = (const float4*)(g_Pb + (size_t)v1 * 64);

    // 16 packed f32x2 accumulators per edge (= 32 h2 outputs), init with b2.
    unsigned long long acc0[16], acc1[16];
    const unsigned long long* b2p = (const unsigned long long*)sb2;
#pragma unroll
    for (int q = 0; q < 16; q++) { acc0[q] = b2p[q]; acc1[q] = b2p[q]; }

#pragma unroll
    for (int kk = 0; kk < 16; kk++) {
        float4 a0 = pa0[kk], c0 = pb0[kk];
        float4 a1 = pa1[kk], c1 = pb1[kk];
        unsigned long long h00 = pack2(fmaxf(a0.x + c0.x, 0.0f));
        unsigned long long h01 = pack2(fmaxf(a0.y + c0.y, 0.0f));
        unsigned long long h02 = pack2(fmaxf(a0.z + c0.z, 0.0f));
        unsigned long long h03 = pack2(fmaxf(a0.w + c0.w, 0.0f));
        unsigned long long h10 = pack2(fmaxf(a1.x + c1.x, 0.0f));
        unsigned long long h11 = pack2(fmaxf(a1.y + c1.y, 0.0f));
        unsigned long long h12 = pack2(fmaxf(a1.z + c1.z, 0.0f));
        unsigned long long h13 = pack2(fmaxf(a1.w + c1.w, 0.0f));

        // 4 rows of W2 (rows 4kk..4kk+3), each row = 32 floats = 8 ulonglong2.
        const ulonglong2* w = (const ulonglong2*)(sW2 + (size_t)(4 * kk) * 32);
#pragma unroll
        for (int q = 0; q < 8; q++) {
            ulonglong2 w0 = w[q];
            ulonglong2 w1 = w[8 + q];
            ulonglong2 w2 = w[16 + q];
            ulonglong2 w3 = w[24 + q];
            unsigned long long t0 = acc0[2 * q],     s0 = acc0[2 * q + 1];
            unsigned long long t1 = acc1[2 * q],     s1 = acc1[2 * q + 1];
            t0 = fma2(h00, w0.x, t0);  s0 = fma2(h00, w0.y, s0);
            t0 = fma2(h01, w1.x, t0);  s0 = fma2(h01, w1.y, s0);
            t0 = fma2(h02, w2.x, t0);  s0 = fma2(h02, w2.y, s0);
            t0 = fma2(h03, w3.x, t0);  s0 = fma2(h03, w3.y, s0);
            t1 = fma2(h10, w0.x, t1);  s1 = fma2(h10, w0.y, s1);
            t1 = fma2(h11, w1.x, t1);  s1 = fma2(h11, w1.y, s1);
            t1 = fma2(h12, w2.x, t1);  s1 = fma2(h12, w2.y, s1);
            t1 = fma2(h13, w3.x, t1);  s1 = fma2(h13, w3.y, s1);
            acc0[2 * q] = t0;  acc0[2 * q + 1] = s0;
            acc1[2 * q] = t1;  acc1[2 * q + 1] = s1;
        }
    }

    // Layer 3 + sigmoid.
    float z0 = sb3, z1 = sb3;
#pragma unroll
    for (int q = 0; q < 16; q++) {
        float lo, hi;
        unpack2(acc0[q], lo, hi);
        z0 = fmaf(fmaxf(lo, 0.0f), sW3[2 * q],     z0);
        z0 = fmaf(fmaxf(hi, 0.0f), sW3[2 * q + 1], z0);
        unpack2(acc1[q], lo, hi);
        z1 = fmaf(fmaxf(lo, 0.0f), sW3[2 * q],     z1);
        z1 = fmaf(fmaxf(hi, 0.0f), sW3[2 * q + 1], z1);
    }
    if (do0) out[e0] = 1.0f / (1.0f + __expf(-z0));
    if (do1) out[e1] = 1.0f / (1.0f + __expf(-z1));
}

__global__ void __launch_bounds__(256)
idx_copy_kernel(const int* __restrict__ ei, float* __restrict__ out, int n) {
    int i = blockIdx.x * blockDim.x + threadIdx.x;
    if (i < n) out[i] = (float)ei[i];
}

extern "C" void kernel_launch(void* const* d_in, const int* in_sizes, int n_in,
                              void* d_out, int out_size) {
    const float* emb = (const float*)d_in[0];
    const int*   ei  = (const int*)d_in[1];
    const float* W1  = (const float*)d_in[2];
    const float* b1  = (const float*)d_in[3];
    const float* W2  = (const float*)d_in[4];
    const float* b2  = (const float*)d_in[5];
    const float* W3  = (const float*)d_in[6];
    const float* b3  = (const float*)d_in[7];

    int n_nodes = in_sizes[0] / 16;
    int E       = in_sizes[1] / 2;
    float* out  = (float*)d_out;

    precompute_kernel<<<(n_nodes + 255) / 256, 256>>>(emb, W1, b1, n_nodes);

    int H = (E + 1) / 2;                 // threads cover edges [0,H) and [H,E)
    edge_kernel<<<(H + 255) / 256, 256>>>(ei, W2, b2, W3, b3, out, E, H);

    if (out_size >= 3 * E) {
        int n = 2 * E;
        idx_copy_kernel<<<(n + 255) / 256, 256>>>(ei, out + E, n);
    }
}

// round 5
// speedup vs baseline: 1.3394x; 1.0787x over previous
#include <cuda_runtime.h>
#include <cuda_bf16.h>

// EdgeDecoder: probs = sigmoid(relu(relu(concat(emb[u],emb[v]) @ W1 + b1) @ W2 + b2) @ W3 + b3)
// R1: concat@W1 factored into per-node partials Pa/Pb (precompute).
// R2: layer2 via packed fma.rn.f32x2.
// R3/R4: LDG-issue bound fix — warp-coalesced gather of Pa/Pb rows into smem
//     (32 scattered LDG.128/edge -> ~2 coalesced LDG.128/edge), single fused
//     gather pass (Pa+Pb add+ReLU in registers), then FFMA2 compute.

#define MAX_NODES 100000
#define HID 64
#define EPB 128           // edges per block
#define HSTRIDE 68        // padded row stride in floats (68*4 = 272 B = 17 x 16 B)

__device__ float g_Pa[(size_t)MAX_NODES * HID];
__device__ float g_Pb[(size_t)MAX_NODES * HID];

// ---- packed f32x2 helpers (sm_100+) ----
__device__ __forceinline__ unsigned long long fma2(unsigned long long a,
                                                   unsigned long long b,
                                                   unsigned long long c) {
    unsigned long long d;
    asm("fma.rn.f32x2 %0, %1, %2, %3;" : "=l"(d) : "l"(a), "l"(b), "l"(c));
    return d;
}
__device__ __forceinline__ unsigned long long pack2(float x) {
    unsigned long long r;
    asm("mov.b64 %0, {%1, %1};" : "=l"(r) : "f"(x));
    return r;
}
__device__ __forceinline__ void unpack2(unsigned long long v, float& lo, float& hi) {
    asm("mov.b64 {%0, %1}, %2;" : "=f"(lo), "=f"(hi) : "l"(v));
}

__global__ void __launch_bounds__(256)
precompute_kernel(const float* __restrict__ emb,
                  const float* __restrict__ W1,
                  const float* __restrict__ b1,
                  int n_nodes) {
    __shared__ float sW1[32 * 64];
    __shared__ float sb1[64];
    for (int i = threadIdx.x; i < 32 * 64; i += blockDim.x) sW1[i] = W1[i];
    if (threadIdx.x < 64) sb1[threadIdx.x] = b1[threadIdx.x];
    __syncthreads();

    int n = blockIdx.x * blockDim.x + threadIdx.x;
    if (n >= n_nodes) return;

    float x[16];
    const float4* e4 = (const float4*)(emb + (size_t)n * 16);
#pragma unroll
    for (int i = 0; i < 4; i++) {
        float4 t = e4[i];
        x[4 * i + 0] = t.x; x[4 * i + 1] = t.y;
        x[4 * i + 2] = t.z; x[4 * i + 3] = t.w;
    }

    float acc[64];
#pragma unroll
    for (int j = 0; j < 64; j++) acc[j] = sb1[j];
#pragma unroll
    for (int k = 0; k < 16; k++)
#pragma unroll
        for (int j = 0; j < 64; j++)
            acc[j] = fmaf(x[k], sW1[k * 64 + j], acc[j]);
    {
        float4* pa = (float4*)(g_Pa + (size_t)n * 64);
#pragma unroll
        for (int j4 = 0; j4 < 16; j4++)
            pa[j4] = make_float4(acc[4 * j4], acc[4 * j4 + 1], acc[4 * j4 + 2], acc[4 * j4 + 3]);
    }

#pragma unroll
    for (int j = 0; j < 64; j++) acc[j] = 0.0f;
#pragma unroll
    for (int k = 0; k < 16; k++)
#pragma unroll
        for (int j = 0; j < 64; j++)
            acc[j] = fmaf(x[k], sW1[(16 + k) * 64 + j], acc[j]);
    {
        float4* pb = (float4*)(g_Pb + (size_t)n * 64);
#pragma unroll
        for (int j4 = 0; j4 < 16; j4++)
            pb[j4] = make_float4(acc[4 * j4], acc[4 * j4 + 1], acc[4 * j4 + 2], acc[4 * j4 + 3]);
    }
}

__global__ void __launch_bounds__(128)
edge_kernel(const int* __restrict__ ei,
            const float* __restrict__ W2,
            const float* __restrict__ b2,
            const float* __restrict__ W3,
            const float* __restrict__ b3,
            float* __restrict__ out,
            int E) {
    __shared__ float sW2[64 * 32];                 // row-major [k][j]
    __shared__ __align__(16) float sW3[32];
    __shared__ __align__(16) float sb2[32];
    __shared__ float sb3;
    __shared__ int sU[EPB], sV[EPB];
    __shared__ __align__(16) float sH[EPB * HSTRIDE];  // relu(Pa[u]+Pb[v]) rows, padded

    const int tid = threadIdx.x;
    const int base = blockIdx.x * EPB;
    const int nE = min(EPB, E - base);

    for (int i = tid; i < 64 * 32; i += 128) sW2[i] = W2[i];
    if (tid < 32) { sW3[tid] = W3[tid]; sb2[tid] = b2[tid]; }
    if (tid == 0) sb3 = b3[0];
    if (tid < nE) { sU[tid] = __ldg(ei + base + tid); sV[tid] = __ldg(ei + (size_t)E + base + tid); }
    else if (tid < EPB) { sU[tid] = 0; sV[tid] = 0; }
    __syncthreads();

    // Fused coalesced gather: for each (edge le, 16B segment s), load Pa seg and
    // Pb seg, add + ReLU in registers, store once. Consecutive 16 lanes cover
    // one row -> coalesced 256B bursts per half-warp.
#pragma unroll
    for (int i = 0; i < 16; i++) {
        int idx = i * 128 + tid;
        int le = idx >> 4;
        int s  = idx & 15;
        if (le < nE) {
            float4 a = __ldg((const float4*)(g_Pa + (size_t)sU[le] * 64) + s);
            float4 v = __ldg((const float4*)(g_Pb + (size_t)sV[le] * 64) + s);
            a.x = fmaxf(a.x + v.x, 0.0f);
            a.y = fmaxf(a.y + v.y, 0.0f);
            a.z = fmaxf(a.z + v.z, 0.0f);
            a.w = fmaxf(a.w + v.w, 0.0f);
            *(float4*)(sH + le * HSTRIDE + s * 4) = a;
        }
    }
    __syncthreads();

    // Phase B: one edge per thread, layer2 via packed FFMA2, layer3 + sigmoid.
    if (tid >= nE) return;

    unsigned long long acc[16];
    const unsigned long long* b2p = (const unsigned long long*)sb2;
#pragma unroll
    for (int q = 0; q < 16; q++) acc[q] = b2p[q];

    const float* hrow = sH + tid * HSTRIDE;
#pragma unroll
    for (int kk = 0; kk < 16; kk++) {
        float4 h4 = *(const float4*)(hrow + kk * 4);
        unsigned long long h0 = pack2(h4.x);
        unsigned long long h1 = pack2(h4.y);
        unsigned long long h2 = pack2(h4.z);
        unsigned long long h3 = pack2(h4.w);

        const ulonglong2* w = (const ulonglong2*)(sW2 + (4 * kk) * 32);
#pragma unroll
        for (int q = 0; q < 8; q++) {
            ulonglong2 w0 = w[q];
            ulonglong2 w1 = w[8 + q];
            ulonglong2 w2 = w[16 + q];
            ulonglong2 w3 = w[24 + q];
            unsigned long long t = acc[2 * q], s = acc[2 * q + 1];
            t = fma2(h0, w0.x, t);  s = fma2(h0, w0.y, s);
            t = fma2(h1, w1.x, t);  s = fma2(h1, w1.y, s);
            t = fma2(h2, w2.x, t);  s = fma2(h2, w2.y, s);
            t = fma2(h3, w3.x, t);  s = fma2(h3, w3.y, s);
            acc[2 * q] = t;  acc[2 * q + 1] = s;
        }
    }

    float z = sb3;
#pragma unroll
    for (int q = 0; q < 16; q++) {
        float lo, hi;
        unpack2(acc[q], lo, hi);
        z = fmaf(fmaxf(lo, 0.0f), sW3[2 * q],     z);
        z = fmaf(fmaxf(hi, 0.0f), sW3[2 * q + 1], z);
    }
    out[base + tid] = 1.0f / (1.0f + __expf(-z));
}

__global__ void __launch_bounds__(256)
idx_copy_kernel(const int* __restrict__ ei, float* __restrict__ out, int n4) {
    int i = blockIdx.x * blockDim.x + threadIdx.x;
    if (i < n4) {
        int4 v = __ldg((const int4*)ei + i);
        float4 f = make_float4((float)v.x, (float)v.y, (float)v.z, (float)v.w);
        ((float4*)out)[i] = f;
    }
}

__global__ void __launch_bounds__(256)
idx_copy_tail_kernel(const int* __restrict__ ei, float* __restrict__ out, int start, int n) {
    int i = start + blockIdx.x * blockDim.x + threadIdx.x;
    if (i < n) out[i] = (float)ei[i];
}

extern "C" void kernel_launch(void* const* d_in, const int* in_sizes, int n_in,
                              void* d_out, int out_size) {
    const float* emb = (const float*)d_in[0];
    const int*   ei  = (const int*)d_in[1];
    const float* W1  = (const float*)d_in[2];
    const float* b1  = (const float*)d_in[3];
    const float* W2  = (const float*)d_in[4];
    const float* b2  = (const float*)d_in[5];
    const float* W3  = (const float*)d_in[6];
    const float* b3  = (const float*)d_in[7];

    int n_nodes = in_sizes[0] / 16;
    int E       = in_sizes[1] / 2;
    float* out  = (float*)d_out;

    precompute_kernel<<<(n_nodes + 255) / 256, 256>>>(emb, W1, b1, n_nodes);

    edge_kernel<<<(E + EPB - 1) / EPB, 128>>>(ei, W2, b2, W3, b3, out, E);

    if (out_size >= 3 * E) {
        int n = 2 * E;
        int n4 = n / 4;
        if (n4 > 0)
            idx_copy_kernel<<<(n4 + 255) / 256, 256>>>(ei, out + E, n4);
        if (n4 * 4 < n)
            idx_copy_tail_kernel<<<1, 256>>>(ei, out + E, n4 * 4, n);
    }
}

// round 7
// speedup vs baseline: 1.6687x; 1.2458x over previous
#include <cuda_runtime.h>
#include <cuda_bf16.h>
#include <cstdint>

// EdgeDecoder: probs = sigmoid(relu(relu(concat(emb[u],emb[v])@W1+b1)@W2+b2)@W3+b3)
// R1: concat@W1 factored into per-node partials Pa/Pb (precompute).
// R6: layer2 on warp-level tensor cores (mma.sync m16n8k16 bf16, sm_80+ path that
//     compiles for plain sm_100 target), 3-term bf16 hi/lo split for fp32-grade
//     precision. Coalesced gather -> padded smem -> ldmatrix -> HMMA -> smem D ->
//     per-edge epilogue.

#define MAX_NODES 100000
#define EPB 128
#define APITCH_B 144      // A row pitch in bytes (72 bf16) — conflict-free ldmatrix
#define DPITCH_F 36       // D row pitch in floats (144 B, 16B-aligned)

__device__ float g_Pa[(size_t)MAX_NODES * 64];
__device__ float g_Pb[(size_t)MAX_NODES * 64];
// Per-lane packed B fragments for mma.sync: [kt][nt][lane] -> uint2 (b0,b1)
__device__ __align__(16) uint2 g_BfragHi[4 * 4 * 32];
__device__ __align__(16) uint2 g_BfragLo[4 * 4 * 32];

// ---- dynamic smem layout ----
#define SM_U    0
#define SM_V    512
#define SM_W3   1024
#define SM_B2   1152
#define SM_B3   1280
#define SM_BH   1536                  // 4096 B
#define SM_BL   (SM_BH + 4096)       // 4096 B
#define SM_AHI  (SM_BL + 4096)       // 128*144 = 18432 B
#define SM_ALO  (SM_AHI + 18432)     // 18432 B
#define SM_D    (SM_ALO + 18432)     // 128*144 = 18432 B
#define SMEM_BYTES (SM_D + 18432)    // 65024 B

__device__ __forceinline__ uint32_t smem_u32(const void* p) {
    uint32_t a;
    asm("{ .reg .u64 t; cvta.to.shared.u64 t, %1; cvt.u32.u64 %0, t; }" : "=r"(a) : "l"(p));
    return a;
}

__device__ __forceinline__ void ldmatrix_x4(uint32_t& a0, uint32_t& a1,
                                            uint32_t& a2, uint32_t& a3, uint32_t addr) {
    asm volatile("ldmatrix.sync.aligned.m8n8.x4.shared.b16 {%0,%1,%2,%3}, [%4];"
                 : "=r"(a0), "=r"(a1), "=r"(a2), "=r"(a3) : "r"(addr));
}

__device__ __forceinline__ void mma_bf16(float* c, uint32_t a0, uint32_t a1,
                                         uint32_t a2, uint32_t a3,
                                         uint32_t b0, uint32_t b1) {
    asm volatile("mma.sync.aligned.m16n8k16.row.col.f32.bf16.bf16.f32 "
                 "{%0,%1,%2,%3},{%4,%5,%6,%7},{%8,%9},{%0,%1,%2,%3};"
                 : "+f"(c[0]), "+f"(c[1]), "+f"(c[2]), "+f"(c[3])
                 : "r"(a0), "r"(a1), "r"(a2), "r"(a3), "r"(b0), "r"(b1));
}

// ---------------- precompute: Pa = emb@W1[:16]+b1, Pb = emb@W1[16:] ----------------
__global__ void __launch_bounds__(256)
precompute_kernel(const float* __restrict__ emb,
                  const float* __restrict__ W1,
                  const float* __restrict__ b1,
                  int n_nodes) {
    __shared__ float sW1[32 * 64];
    __shared__ float sb1[64];
    for (int i = threadIdx.x; i < 32 * 64; i += blockDim.x) sW1[i] = W1[i];
    if (threadIdx.x < 64) sb1[threadIdx.x] = b1[threadIdx.x];
    __syncthreads();

    int n = blockIdx.x * blockDim.x + threadIdx.x;
    if (n >= n_nodes) return;

    float x[16];
    const float4* e4 = (const float4*)(emb + (size_t)n * 16);
#pragma unroll
    for (int i = 0; i < 4; i++) {
        float4 t = e4[i];
        x[4 * i + 0] = t.x; x[4 * i + 1] = t.y;
        x[4 * i + 2] = t.z; x[4 * i + 3] = t.w;
    }
    float acc[64];
#pragma unroll
    for (int j = 0; j < 64; j++) acc[j] = sb1[j];
#pragma unroll
    for (int k = 0; k < 16; k++)
#pragma unroll
        for (int j = 0; j < 64; j++)
            acc[j] = fmaf(x[k], sW1[k * 64 + j], acc[j]);
    {
        float4* pa = (float4*)(g_Pa + (size_t)n * 64);
#pragma unroll
        for (int j4 = 0; j4 < 16; j4++)
            pa[j4] = make_float4(acc[4 * j4], acc[4 * j4 + 1], acc[4 * j4 + 2], acc[4 * j4 + 3]);
    }
#pragma unroll
    for (int j = 0; j < 64; j++) acc[j] = 0.0f;
#pragma unroll
    for (int k = 0; k < 16; k++)
#pragma unroll
        for (int j = 0; j < 64; j++)
            acc[j] = fmaf(x[k], sW1[(16 + k) * 64 + j], acc[j]);
    {
        float4* pb = (float4*)(g_Pb + (size_t)n * 64);
#pragma unroll
        for (int j4 = 0; j4 < 16; j4++)
            pb[j4] = make_float4(acc[4 * j4], acc[4 * j4 + 1], acc[4 * j4 + 2], acc[4 * j4 + 3]);
    }
}

// ---------------- prep: per-lane packed B fragments (W2 hi/lo split) ----------------
__global__ void __launch_bounds__(128)
prep_bfrag(const float* __restrict__ W2) {
    for (int e = threadIdx.x; e < 512; e += 128) {
        int lane = e & 31;
        int nt = (e >> 5) & 3;
        int kt = e >> 7;
        int n  = nt * 8 + (lane >> 2);
        int k0 = kt * 16 + (lane & 3) * 2;
        float w00 = W2[(k0 + 0) * 32 + n];
        float w01 = W2[(k0 + 1) * 32 + n];
        float w10 = W2[(k0 + 8) * 32 + n];
        float w11 = W2[(k0 + 9) * 32 + n];

        __nv_bfloat162 h0 = __floats2bfloat162_rn(w00, w01);
        __nv_bfloat162 h1 = __floats2bfloat162_rn(w10, w11);
        __nv_bfloat162 l0 = __floats2bfloat162_rn(w00 - __bfloat162float(h0.x),
                                                  w01 - __bfloat162float(h0.y));
        __nv_bfloat162 l1 = __floats2bfloat162_rn(w10 - __bfloat162float(h1.x),
                                                  w11 - __bfloat162float(h1.y));
        g_BfragHi[e] = make_uint2(*(uint32_t*)&h0, *(uint32_t*)&h1);
        g_BfragLo[e] = make_uint2(*(uint32_t*)&l0, *(uint32_t*)&l1);
    }
}

// ---------------- edge kernel: gather -> ldmatrix/HMMA (3-term) -> epilogue ----------------
__global__ void __launch_bounds__(128)
edge_kernel(const int* __restrict__ ei,
            const float* __restrict__ b2,
            const float* __restrict__ W3,
            const float* __restrict__ b3,
            float* __restrict__ out,
            int E) {
    extern __shared__ char smem[];
    const uint32_t sbase = smem_u32(smem);
    const int tid = threadIdx.x;
    const int wid = tid >> 5, lid = tid & 31;

    int*   sU  = (int*)(smem + SM_U);
    int*   sV  = (int*)(smem + SM_V);
    float* sW3 = (float*)(smem + SM_W3);
    float* sB2 = (float*)(smem + SM_B2);
    const uint2* sBH = (const uint2*)(smem + SM_BH);
    const uint2* sBL = (const uint2*)(smem + SM_BL);

    if (tid < 32) { sW3[tid] = W3[tid]; sB2[tid] = b2[tid]; }
    if (tid == 0) *(float*)(smem + SM_B3) = b3[0];
    {
        uint2* dh = (uint2*)(smem + SM_BH);
        uint2* dl = (uint2*)(smem + SM_BL);
        for (int i = tid; i < 512; i += 128) { dh[i] = g_BfragHi[i]; dl[i] = g_BfragLo[i]; }
    }

    const int base = blockIdx.x * EPB;
    const int nE = min(EPB, E - base);
    if (tid < nE) { sU[tid] = __ldg(ei + base + tid); sV[tid] = __ldg(ei + (size_t)E + base + tid); }
    else          { sU[tid] = 0; sV[tid] = 0; }
    __syncthreads();

    // Coalesced gather: 16 lanes per edge row. relu(Pa[u]+Pb[v]) -> bf16 hi/lo.
#pragma unroll
    for (int i = 0; i < 16; i++) {
        int idx = i * 128 + tid;
        int le = idx >> 4;
        int s  = idx & 15;
        float4 a = __ldg((const float4*)(g_Pa + (size_t)sU[le] * 64) + s);
        float4 v = __ldg((const float4*)(g_Pb + (size_t)sV[le] * 64) + s);
        float x0 = fmaxf(a.x + v.x, 0.0f);
        float x1 = fmaxf(a.y + v.y, 0.0f);
        float x2 = fmaxf(a.z + v.z, 0.0f);
        float x3 = fmaxf(a.w + v.w, 0.0f);
        __nv_bfloat162 h01 = __floats2bfloat162_rn(x0, x1);
        __nv_bfloat162 h23 = __floats2bfloat162_rn(x2, x3);
        __nv_bfloat162 l01 = __floats2bfloat162_rn(x0 - __bfloat162float(h01.x),
                                                   x1 - __bfloat162float(h01.y));
        __nv_bfloat162 l23 = __floats2bfloat162_rn(x2 - __bfloat162float(h23.x),
                                                   x3 - __bfloat162float(h23.y));
        uint32_t off = (uint32_t)le * APITCH_B + (uint32_t)s * 8;
        *(uint2*)(smem + SM_AHI + off) = make_uint2(*(uint32_t*)&h01, *(uint32_t*)&h23);
        *(uint2*)(smem + SM_ALO + off) = make_uint2(*(uint32_t*)&l01, *(uint32_t*)&l23);
    }
    __syncthreads();

    // Warp-level GEMM: each warp computes 32 rows x 32 cols, K=64.
    float acc[2][4][4];
#pragma unroll
    for (int mt = 0; mt < 2; mt++)
#pragma unroll
        for (int nt = 0; nt < 4; nt++)
#pragma unroll
            for (int r = 0; r < 4; r++) acc[mt][nt][r] = 0.0f;

    const int r0 = wid * 32;
    const uint32_t lrow = (uint32_t)(lid & 15);
    const uint32_t lcol = (uint32_t)((lid >> 4) * 16);  // bytes

#pragma unroll
    for (int kt = 0; kt < 4; kt++) {
        uint32_t ah[2][4], al[2][4];
#pragma unroll
        for (int mt = 0; mt < 2; mt++) {
            uint32_t rowb = (uint32_t)(r0 + mt * 16) + lrow;
            uint32_t cb   = (uint32_t)kt * 32 + lcol;
            ldmatrix_x4(ah[mt][0], ah[mt][1], ah[mt][2], ah[mt][3],
                        sbase + SM_AHI + rowb * APITCH_B + cb);
            ldmatrix_x4(al[mt][0], al[mt][1], al[mt][2], al[mt][3],
                        sbase + SM_ALO + rowb * APITCH_B + cb);
        }
#pragma unroll
        for (int nt = 0; nt < 4; nt++) {
            uint2 bh = sBH[(kt * 4 + nt) * 32 + lid];
            uint2 bl = sBL[(kt * 4 + nt) * 32 + lid];
#pragma unroll
            for (int mt = 0; mt < 2; mt++) {
                mma_bf16(acc[mt][nt], ah[mt][0], ah[mt][1], ah[mt][2], ah[mt][3], bh.x, bh.y);
                mma_bf16(acc[mt][nt], al[mt][0], al[mt][1], al[mt][2], al[mt][3], bh.x, bh.y);
                mma_bf16(acc[mt][nt], ah[mt][0], ah[mt][1], ah[mt][2], ah[mt][3], bl.x, bl.y);
            }
        }
    }

    // Store D tiles to smem (pitch 36 floats = 144B).
    float* sD = (float*)(smem + SM_D);
#pragma unroll
    for (int mt = 0; mt < 2; mt++) {
        int rA = r0 + mt * 16 + (lid >> 2);
        int rB = rA + 8;
        int cb = (lid & 3) * 2;
#pragma unroll
        for (int nt = 0; nt < 4; nt++) {
            int c = nt * 8 + cb;
            *(float2*)(sD + rA * DPITCH_F + c) = make_float2(acc[mt][nt][0], acc[mt][nt][1]);
            *(float2*)(sD + rB * DPITCH_F + c) = make_float2(acc[mt][nt][2], acc[mt][nt][3]);
        }
    }
    __syncwarp();

    // Epilogue: thread tid handles edge tid (same warp wrote its D rows).
    if (tid < nE) {
        const float b3s = *(const float*)(smem + SM_B3);
        float z = b3s;
        const float4* drow = (const float4*)(sD + tid * DPITCH_F);
#pragma unroll
        for (int q = 0; q < 8; q++) {
            float4 d = drow[q];
            z = fmaf(fmaxf(d.x + sB2[4 * q + 0], 0.0f), sW3[4 * q + 0], z);
            z = fmaf(fmaxf(d.y + sB2[4 * q + 1], 0.0f), sW3[4 * q + 1], z);
            z = fmaf(fmaxf(d.z + sB2[4 * q + 2], 0.0f), sW3[4 * q + 2], z);
            z = fmaf(fmaxf(d.w + sB2[4 * q + 3], 0.0f), sW3[4 * q + 3], z);
        }
        out[base + tid] = 1.0f / (1.0f + __expf(-z));
    }
}

// ---------------- edge_index passthrough ----------------
__global__ void __launch_bounds__(256)
idx_copy_kernel(const int* __restrict__ ei, float* __restrict__ out, int n4) {
    int i = blockIdx.x * blockDim.x + threadIdx.x;
    if (i < n4) {
        int4 v = __ldg((const int4*)ei + i);
        ((float4*)out)[i] = make_float4((float)v.x, (float)v.y, (float)v.z, (float)v.w);
    }
}
__global__ void __launch_bounds__(256)
idx_copy_tail_kernel(const int* __restrict__ ei, float* __restrict__ out, int start, int n) {
    int i = start + blockIdx.x * blockDim.x + threadIdx.x;
    if (i < n) out[i] = (float)ei[i];
}

extern "C" void kernel_launch(void* const* d_in, const int* in_sizes, int n_in,
                              void* d_out, int out_size) {
    const float* emb = (const float*)d_in[0];
    const int*   ei  = (const int*)d_in[1];
    const float* W1  = (const float*)d_in[2];
    const float* b1  = (const float*)d_in[3];
    const float* W2  = (const float*)d_in[4];
    const float* b2  = (const float*)d_in[5];
    const float* W3  = (const float*)d_in[6];
    const float* b3  = (const float*)d_in[7];

    int n_nodes = in_sizes[0] / 16;
    int E       = in_sizes[1] / 2;
    float* out  = (float*)d_out;

    static bool attr_set = false;
    if (!attr_set) {
        cudaFuncSetAttribute(edge_kernel, cudaFuncAttributeMaxDynamicSharedMemorySize, SMEM_BYTES);
        attr_set = true;
    }

    precompute_kernel<<<(n_nodes + 255) / 256, 256>>>(emb, W1, b1, n_nodes);
    prep_bfrag<<<1, 128>>>(W2);

    edge_kernel<<<(E + EPB - 1) / EPB, 128, SMEM_BYTES>>>(ei, b2, W3, b3, out, E);

    if (out_size >= 3 * E) {
        int n = 2 * E;
        int n4 = n / 4;
        if (n4 > 0)
            idx_copy_kernel<<<(n4 + 255) / 256, 256>>>(ei, out + E, n4);
        if (n4 * 4 < n)
            idx_copy_tail_kernel<<<1, 256>>>(ei, out + E, n4 * 4, n);
    }
}

// round 9
// speedup vs baseline: 2.0768x; 1.2446x over previous
#include <cuda_runtime.h>
#include <cuda_bf16.h>
#include <cstdint>

// EdgeDecoder: probs = sigmoid(relu(relu(concat(emb[u],emb[v])@W1+b1)@W2+b2)@W3+b3)
// R1: concat@W1 factored into per-node partials Pa/Pb (precompute).
// R6: layer2 on warp-level tensor cores (mma.sync m16n8k16 bf16), 3-term hi/lo split.
// R8/R9: occupancy fix — 8 warps/block (16x32 tile per warp), D aliased onto A_hi
//     (smem 65KB -> 46.5KB, 4 CTAs/SM, 32 warps/SM), 4-way split precompute.

#define MAX_NODES 100000
#define EPB 128
#define APITCH_B 144      // A row pitch in bytes (72 bf16) — conflict-free ldmatrix
#define DPITCH_F 36       // D row pitch in floats (144 B)

__device__ float g_Pa[(size_t)MAX_NODES * 64];
__device__ float g_Pb[(size_t)MAX_NODES * 64];
// Per-lane packed B fragments for mma.sync: [kt][nt][lane] -> uint2 (b0,b1)
__device__ __align__(16) uint2 g_BfragHi[4 * 4 * 32];
__device__ __align__(16) uint2 g_BfragLo[4 * 4 * 32];

__device__ __forceinline__ uint32_t smem_u32(const void* p) {
    uint32_t a;
    asm("{ .reg .u64 t; cvta.to.shared.u64 t, %1; cvt.u32.u64 %0, t; }" : "=r"(a) : "l"(p));
    return a;
}

__device__ __forceinline__ void ldmatrix_x4(uint32_t& a0, uint32_t& a1,
                                            uint32_t& a2, uint32_t& a3, uint32_t addr) {
    asm volatile("ldmatrix.sync.aligned.m8n8.x4.shared.b16 {%0,%1,%2,%3}, [%4];"
                 : "=r"(a0), "=r"(a1), "=r"(a2), "=r"(a3) : "r"(addr));
}

__device__ __forceinline__ void mma_bf16(float* c, uint32_t a0, uint32_t a1,
                                         uint32_t a2, uint32_t a3,
                                         uint32_t b0, uint32_t b1) {
    asm volatile("mma.sync.aligned.m16n8k16.row.col.f32.bf16.bf16.f32 "
                 "{%0,%1,%2,%3},{%4,%5,%6,%7},{%8,%9},{%0,%1,%2,%3};"
                 : "+f"(c[0]), "+f"(c[1]), "+f"(c[2]), "+f"(c[3])
                 : "r"(a0), "r"(a1), "r"(a2), "r"(a3), "r"(b0), "r"(b1));
}

// ---------------- precompute (4-way split: node x {Pa,Pb} x col-half) ----------------
__global__ void __launch_bounds__(256)
precompute_kernel(const float* __restrict__ emb,
                  const float* __restrict__ W1,
                  const float* __restrict__ b1,
                  int n_nodes) {
    __shared__ float sW1[32 * 64];
    __shared__ float sb1[64];
    for (int i = threadIdx.x; i < 32 * 64; i += blockDim.x) sW1[i] = W1[i];
    if (threadIdx.x < 64) sb1[threadIdx.x] = b1[threadIdx.x];
    __syncthreads();

    int t = blockIdx.x * blockDim.x + threadIdx.x;
    int n = t >> 2;
    if (n >= n_nodes) return;
    int part = (t >> 1) & 1;          // 0 -> Pa (W1 rows 0..15, +b1), 1 -> Pb (rows 16..31)
    int ch   = t & 1;                 // output col half: 0 -> 0..31, 1 -> 32..63

    float x[16];
    const float4* e4 = (const float4*)(emb + (size_t)n * 16);
#pragma unroll
    for (int i = 0; i < 4; i++) {
        float4 v = e4[i];
        x[4 * i + 0] = v.x; x[4 * i + 1] = v.y;
        x[4 * i + 2] = v.z; x[4 * i + 3] = v.w;
    }

    const int j0 = ch * 32;
    const int kbase = part * 16;
    float acc[32];
#pragma unroll
    for (int j = 0; j < 32; j++) acc[j] = part ? 0.0f : sb1[j0 + j];
#pragma unroll
    for (int k = 0; k < 16; k++)
#pragma unroll
        for (int j = 0; j < 32; j++)
            acc[j] = fmaf(x[k], sW1[(kbase + k) * 64 + j0 + j], acc[j]);

    float* dst = (part ? g_Pb : g_Pa) + (size_t)n * 64 + j0;
    float4* d4 = (float4*)dst;
#pragma unroll
    for (int j4 = 0; j4 < 8; j4++)
        d4[j4] = make_float4(acc[4 * j4], acc[4 * j4 + 1], acc[4 * j4 + 2], acc[4 * j4 + 3]);
}

// ---------------- prep: per-lane packed B fragments (W2 hi/lo split) ----------------
__global__ void __launch_bounds__(128)
prep_bfrag(const float* __restrict__ W2) {
    for (int e = threadIdx.x; e < 512; e += 128) {
        int lane = e & 31;
        int nt = (e >> 5) & 3;
        int kt = e >> 7;
        int n  = nt * 8 + (lane >> 2);
        int k0 = kt * 16 + (lane & 3) * 2;
        float w00 = W2[(k0 + 0) * 32 + n];
        float w01 = W2[(k0 + 1) * 32 + n];
        float w10 = W2[(k0 + 8) * 32 + n];
        float w11 = W2[(k0 + 9) * 32 + n];

        __nv_bfloat162 h0 = __floats2bfloat162_rn(w00, w01);
        __nv_bfloat162 h1 = __floats2bfloat162_rn(w10, w11);
        __nv_bfloat162 l0 = __floats2bfloat162_rn(w00 - __bfloat162float(h0.x),
                                                  w01 - __bfloat162float(h0.y));
        __nv_bfloat162 l1 = __floats2bfloat162_rn(w10 - __bfloat162float(h1.x),
                                                  w11 - __bfloat162float(h1.y));
        g_BfragHi[e] = make_uint2(*(uint32_t*)&h0, *(uint32_t*)&h1);
        g_BfragLo[e] = make_uint2(*(uint32_t*)&l0, *(uint32_t*)&l1);
    }
}

// ---------------- edge kernel: gather -> ldmatrix/HMMA (3-term) -> epilogue ----------------
__global__ void __launch_bounds__(256, 4)
edge_kernel(const int* __restrict__ ei,
            const float* __restrict__ b2,
            const float* __restrict__ W3,
            const float* __restrict__ b3,
            float* __restrict__ out,
            int E) {
    __shared__ int sU[EPB], sV[EPB];
    __shared__ float sW3[32], sB2[32];
    __shared__ float sB3;
    __shared__ __align__(16) uint2 sBH[512], sBL[512];
    __shared__ __align__(16) unsigned char sAhi[EPB * APITCH_B];
    __shared__ __align__(16) unsigned char sAlo[EPB * APITCH_B];
    float* sD = (float*)sAhi;                       // D aliases A_hi (dead after MMA)

    const int tid = threadIdx.x;
    const int wid = tid >> 5, lid = tid & 31;

    if (tid < 32) { sW3[tid] = W3[tid]; sB2[tid] = b2[tid]; }
    if (tid == 0) sB3 = b3[0];
    for (int i = tid; i < 512; i += 256) { sBH[i] = g_BfragHi[i]; sBL[i] = g_BfragLo[i]; }

    const int base = blockIdx.x * EPB;
    const int nE = min(EPB, E - base);
    if (tid < EPB) {
        if (tid < nE) { sU[tid] = __ldg(ei + base + tid); sV[tid] = __ldg(ei + (size_t)E + base + tid); }
        else          { sU[tid] = 0; sV[tid] = 0; }
    }
    __syncthreads();

    // Coalesced gather: 16 lanes per edge row. relu(Pa[u]+Pb[v]) -> bf16 hi/lo.
    // Issue both LDGs before arithmetic to keep MLP=2 per iteration.
#pragma unroll
    for (int i = 0; i < 8; i++) {
        int idx = i * 256 + tid;
        int le = idx >> 4;
        int s  = idx & 15;
        const float4* pa = (const float4*)(g_Pa + (size_t)sU[le] * 64) + s;
        const float4* pb = (const float4*)(g_Pb + (size_t)sV[le] * 64) + s;
        float4 a = __ldg(pa);
        float4 v = __ldg(pb);
        float x0 = fmaxf(a.x + v.x, 0.0f);
        float x1 = fmaxf(a.y + v.y, 0.0f);
        float x2 = fmaxf(a.z + v.z, 0.0f);
        float x3 = fmaxf(a.w + v.w, 0.0f);
        __nv_bfloat162 h01 = __floats2bfloat162_rn(x0, x1);
        __nv_bfloat162 h23 = __floats2bfloat162_rn(x2, x3);
        __nv_bfloat162 l01 = __floats2bfloat162_rn(x0 - __bfloat162float(h01.x),
                                                   x1 - __bfloat162float(h01.y));
        __nv_bfloat162 l23 = __floats2bfloat162_rn(x2 - __bfloat162float(h23.x),
                                                   x3 - __bfloat162float(h23.y));
        uint32_t off = (uint32_t)le * APITCH_B + (uint32_t)s * 8;
        *(uint2*)(sAhi + off) = make_uint2(*(uint32_t*)&h01, *(uint32_t*)&h23);
        *(uint2*)(sAlo + off) = make_uint2(*(uint32_t*)&l01, *(uint32_t*)&l23);
    }
    __syncthreads();

    // Warp-level GEMM: each of 8 warps computes 16 rows x 32 cols, K=64.
    float acc[4][4];
#pragma unroll
    for (int nt = 0; nt < 4; nt++)
#pragma unroll
        for (int r = 0; r < 4; r++) acc[nt][r] = 0.0f;

    const int r0 = wid * 16;
    const uint32_t ah_base = smem_u32(sAhi);
    const uint32_t al_base = smem_u32(sAlo);
    const uint32_t lrow = (uint32_t)(lid & 15);
    const uint32_t lcol = (uint32_t)((lid >> 4) * 16);  // bytes

#pragma unroll
    for (int kt = 0; kt < 4; kt++) {
        uint32_t ah0, ah1, ah2, ah3, al0, al1, al2, al3;
        uint32_t rowoff = ((uint32_t)r0 + lrow) * APITCH_B + (uint32_t)kt * 32 + lcol;
        ldmatrix_x4(ah0, ah1, ah2, ah3, ah_base + rowoff);
        ldmatrix_x4(al0, al1, al2, al3, al_base + rowoff);
#pragma unroll
        for (int nt = 0; nt < 4; nt++) {
            uint2 bh = sBH[(kt * 4 + nt) * 32 + lid];
            uint2 bl = sBL[(kt * 4 + nt) * 32 + lid];
            mma_bf16(acc[nt], ah0, ah1, ah2, ah3, bh.x, bh.y);
            mma_bf16(acc[nt], al0, al1, al2, al3, bh.x, bh.y);
            mma_bf16(acc[nt], ah0, ah1, ah2, ah3, bl.x, bl.y);
        }
    }
    __syncthreads();   // all ldmatrix reads of A done before D overwrites it

    // Store D tiles (pitch 36 floats).
    {
        int rA = r0 + (lid >> 2);
        int rB = rA + 8;
        int cb = (lid & 3) * 2;
#pragma unroll
        for (int nt = 0; nt < 4; nt++) {
            int c = nt * 8 + cb;
            *(float2*)(sD + rA * DPITCH_F + c) = make_float2(acc[nt][0], acc[nt][1]);
            *(float2*)(sD + rB * DPITCH_F + c) = make_float2(acc[nt][2], acc[nt][3]);
        }
    }
    __syncthreads();

    // Epilogue: thread tid (<128) handles edge tid.
    if (tid < nE) {
        float z = sB3;
        const float4* drow = (const float4*)(sD + tid * DPITCH_F);
#pragma unroll
        for (int q = 0; q < 8; q++) {
            float4 d = drow[q];
            z = fmaf(fmaxf(d.x + sB2[4 * q + 0], 0.0f), sW3[4 * q + 0], z);
            z = fmaf(fmaxf(d.y + sB2[4 * q + 1], 0.0f), sW3[4 * q + 1], z);
            z = fmaf(fmaxf(d.z + sB2[4 * q + 2], 0.0f), sW3[4 * q + 2], z);
            z = fmaf(fmaxf(d.w + sB2[4 * q + 3], 0.0f), sW3[4 * q + 3], z);
        }
        out[base + tid] = 1.0f / (1.0f + __expf(-z));
    }
}

// ---------------- edge_index passthrough ----------------
__global__ void __launch_bounds__(256)
idx_copy_kernel(const int* __restrict__ ei, float* __restrict__ out, int n4) {
    int i = blockIdx.x * blockDim.x + threadIdx.x;
    if (i < n4) {
        int4 v = __ldg((const int4*)ei + i);
        ((float4*)out)[i] = make_float4((float)v.x, (float)v.y, (float)v.z, (float)v.w);
    }
}
__global__ void __launch_bounds__(256)
idx_copy_tail_kernel(const int* __restrict__ ei, float* __restrict__ out, int start, int n) {
    int i = start + blockIdx.x * blockDim.x + threadIdx.x;
    if (i < n) out[i] = (float)ei[i];
}

extern "C" void kernel_launch(void* const* d_in, const int* in_sizes, int n_in,
                              void* d_out, int out_size) {
    const float* emb = (const float*)d_in[0];
    const int*   ei  = (const int*)d_in[1];
    const float* W1  = (const float*)d_in[2];
    const float* b1  = (const float*)d_in[3];
    const float* W2  = (const float*)d_in[4];
    const float* b2  = (const float*)d_in[5];
    const float* W3  = (const float*)d_in[6];
    const float* b3  = (const float*)d_in[7];

    int n_nodes = in_sizes[0] / 16;
    int E       = in_sizes[1] / 2;
    float* out  = (float*)d_out;

    precompute_kernel<<<(4 * n_nodes + 255) / 256, 256>>>(emb, W1, b1, n_nodes);
    prep_bfrag<<<1, 128>>>(W2);

    edge_kernel<<<(E + EPB - 1) / EPB, 256>>>(ei, b2, W3, b3, out, E);

    if (out_size >= 3 * E) {
        int n = 2 * E;
        int n4 = n / 4;
        if (n4 > 0)
            idx_copy_kernel<<<(n4 + 255) / 256, 256>>>(ei, out + E, n4);
        if (n4 * 4 < n)
            idx_copy_tail_kernel<<<1, 256>>>(ei, out + E, n4 * 4, n);
    }
}

// round 10
// speedup vs baseline: 2.7263x; 1.3127x over previous
#include <cuda_runtime.h>
#include <cuda_bf16.h>
#include <cstdint>

// EdgeDecoder: probs = sigmoid(relu(relu(concat(emb[u],emb[v])@W1+b1)@W2+b2)@W3+b3)
// R10: FULLY FUSED tensor-core version. Gather raw emb (128B/edge, 4x less L2
// traffic than Pa/Pb), layer1 MMA (K=32) -> in-register bias+ReLU+bf16-resplit
// (C-fragment of layer1 == A-fragment of layer2) -> layer2 MMA (K=64) -> epilogue.
// Both layers use 3-term bf16 hi/lo splits (fp32-grade precision). edge_index
// passthrough folded into the epilogue (threads 128-255).

#define EPB 128
#define APITCH 80        // A row pitch bytes (64B emb-pair data + 16 pad)
#define DPITCH_F 36      // D row pitch floats (144 B)

// Per-lane packed fragments (prep kernel): W1 [kt1(2)][j(8)][lane], W2 [kt(4)][nt(4)][lane]
__device__ __align__(16) uint2 g_W1fragHi[512];
__device__ __align__(16) uint2 g_W1fragLo[512];
__device__ __align__(16) uint2 g_W2fragHi[512];
__device__ __align__(16) uint2 g_W2fragLo[512];

__device__ __forceinline__ uint32_t smem_u32(const void* p) {
    uint32_t a;
    asm("{ .reg .u64 t; cvta.to.shared.u64 t, %1; cvt.u32.u64 %0, t; }" : "=r"(a) : "l"(p));
    return a;
}
__device__ __forceinline__ void ldmatrix_x4(uint32_t& a0, uint32_t& a1,
                                            uint32_t& a2, uint32_t& a3, uint32_t addr) {
    asm volatile("ldmatrix.sync.aligned.m8n8.x4.shared.b16 {%0,%1,%2,%3}, [%4];"
                 : "=r"(a0), "=r"(a1), "=r"(a2), "=r"(a3) : "r"(addr));
}
__device__ __forceinline__ void mma_bf16(float* c, uint32_t a0, uint32_t a1,
                                         uint32_t a2, uint32_t a3,
                                         uint32_t b0, uint32_t b1) {
    asm volatile("mma.sync.aligned.m16n8k16.row.col.f32.bf16.bf16.f32 "
                 "{%0,%1,%2,%3},{%4,%5,%6,%7},{%8,%9},{%0,%1,%2,%3};"
                 : "+f"(c[0]), "+f"(c[1]), "+f"(c[2]), "+f"(c[3])
                 : "r"(a0), "r"(a1), "r"(a2), "r"(a3), "r"(b0), "r"(b1));
}
__device__ __forceinline__ uint32_t pack_hi(float a, float b) {
    __nv_bfloat162 h = __floats2bfloat162_rn(a, b);
    return *(uint32_t*)&h;
}
__device__ __forceinline__ uint32_t pack_lo(float a, float b, uint32_t hi) {
    __nv_bfloat162 h = *(__nv_bfloat162*)&hi;
    __nv_bfloat162 l = __floats2bfloat162_rn(a - __bfloat162float(h.x),
                                             b - __bfloat162float(h.y));
    return *(uint32_t*)&l;
}

// ---------------- prep: per-lane packed W1/W2 fragments (hi/lo split) ----------------
__global__ void __launch_bounds__(256)
prep_frags(const float* __restrict__ W1, const float* __restrict__ W2) {
    int tid = threadIdx.x;
    for (int e = tid; e < 512; e += 256) {
        int lane = e & 31;
        {   // W1 [32 x 64]: e = kt1*256 + j*32 + lane
            int kt1 = e >> 8, j = (e >> 5) & 7;
            int k0 = kt1 * 16 + (lane & 3) * 2;
            int n  = j * 8 + (lane >> 2);
            float p00 = W1[(k0 + 0) * 64 + n], p01 = W1[(k0 + 1) * 64 + n];
            float p10 = W1[(k0 + 8) * 64 + n], p11 = W1[(k0 + 9) * 64 + n];
            uint32_t h0 = pack_hi(p00, p01), h1 = pack_hi(p10, p11);
            g_W1fragHi[e] = make_uint2(h0, h1);
            g_W1fragLo[e] = make_uint2(pack_lo(p00, p01, h0), pack_lo(p10, p11, h1));
        }
        {   // W2 [64 x 32]: e = kt*128 + nt*32 + lane
            int kt = e >> 7, nt = (e >> 5) & 3;
            int k0 = kt * 16 + (lane & 3) * 2;
            int n  = nt * 8 + (lane >> 2);
            float p00 = W2[(k0 + 0) * 32 + n], p01 = W2[(k0 + 1) * 32 + n];
            float p10 = W2[(k0 + 8) * 32 + n], p11 = W2[(k0 + 9) * 32 + n];
            uint32_t h0 = pack_hi(p00, p01), h1 = pack_hi(p10, p11);
            g_W2fragHi[e] = make_uint2(h0, h1);
            g_W2fragLo[e] = make_uint2(pack_lo(p00, p01, h0), pack_lo(p10, p11, h1));
        }
    }
}

// ---------------- fused edge kernel ----------------
__global__ void __launch_bounds__(256, 4)
edge_kernel(const float* __restrict__ emb,
            const int* __restrict__ ei,
            const float* __restrict__ b1,
            const float* __restrict__ b2,
            const float* __restrict__ W3,
            const float* __restrict__ b3,
            float* __restrict__ out,
            int E, int do_idx) {
    __shared__ __align__(16) unsigned char sA[EPB * APITCH * 2];   // hi | lo; D aliases
    __shared__ __align__(16) uint2 sW1H[512], sW1L[512], sW2H[512], sW2L[512];
    __shared__ int sU[EPB], sV[EPB];
    __shared__ __align__(16) float sB1[64];
    __shared__ __align__(16) float sB2[32], sW3[32];
    __shared__ float sB3;

    unsigned char* sAhi = sA;
    unsigned char* sAlo = sA + EPB * APITCH;
    float* sD = (float*)sA;      // aliases A (dead after ldmatrix)

    const int tid = threadIdx.x;
    const int wid = tid >> 5, lid = tid & 31;
    const int q = lid & 3;

    for (int i = tid; i < 512; i += 256) {
        sW1H[i] = g_W1fragHi[i]; sW1L[i] = g_W1fragLo[i];
        sW2H[i] = g_W2fragHi[i]; sW2L[i] = g_W2fragLo[i];
    }
    if (tid < 64) sB1[tid] = b1[tid];
    if (tid < 32) { sB2[tid] = b2[tid]; sW3[tid] = W3[tid]; }
    if (tid == 0) sB3 = b3[0];

    const int base = blockIdx.x * EPB;
    const int nE = min(EPB, E - base);
    if (tid < EPB) {
        if (tid < nE) { sU[tid] = __ldg(ei + base + tid); sV[tid] = __ldg(ei + (size_t)E + base + tid); }
        else          { sU[tid] = 0; sV[tid] = 0; }
    }
    __syncthreads();

    // Gather raw embeddings: 4 lanes cover one node row (64B). Split to bf16 hi/lo.
#pragma unroll
    for (int i = 0; i < 4; i++) {
        int idx = i * 256 + tid;
        int le = idx >> 3;
        int which = (idx >> 2) & 1;
        int s = idx & 3;
        int node = which ? sV[le] : sU[le];
        float4 v = __ldg((const float4*)(emb + (size_t)node * 16) + s);
        uint32_t h01 = pack_hi(v.x, v.y), h23 = pack_hi(v.z, v.w);
        uint32_t l01 = pack_lo(v.x, v.y, h01), l23 = pack_lo(v.z, v.w, h23);
        uint32_t off = (uint32_t)le * APITCH + (uint32_t)which * 32 + (uint32_t)s * 8;
        *(uint2*)(sAhi + off) = make_uint2(h01, h23);
        *(uint2*)(sAlo + off) = make_uint2(l01, l23);
    }
    __syncthreads();

    // Load emb A fragments (2 k-tiles, hi+lo). Warp computes rows [wid*16, +16).
    const int r0 = wid * 16;
    const uint32_t abh = smem_u32(sAhi);
    const uint32_t abl = smem_u32(sAlo);
    const uint32_t rowoff = ((uint32_t)r0 + (uint32_t)(lid & 15)) * APITCH + ((uint32_t)(lid >> 4)) * 16;
    uint32_t eh[2][4], el[2][4];
    ldmatrix_x4(eh[0][0], eh[0][1], eh[0][2], eh[0][3], abh + rowoff);
    ldmatrix_x4(eh[1][0], eh[1][1], eh[1][2], eh[1][3], abh + rowoff + 32);
    ldmatrix_x4(el[0][0], el[0][1], el[0][2], el[0][3], abl + rowoff);
    ldmatrix_x4(el[1][0], el[1][1], el[1][2], el[1][3], abl + rowoff + 32);
    __syncthreads();    // A smem dead -> D may overwrite it later

    float acc2[4][4];
#pragma unroll
    for (int nt = 0; nt < 4; nt++)
#pragma unroll
        for (int r = 0; r < 4; r++) acc2[nt][r] = 0.0f;

#pragma unroll
    for (int t = 0; t < 4; t++) {
        // ---- layer1: n-tiles j = 2t, 2t+1 (K=32 over 2 k-tiles, 3-term split) ----
        float a1[4] = {0, 0, 0, 0}, a1b[4] = {0, 0, 0, 0};
        {
            int j = 2 * t;
            uint2 w0h = sW1H[j * 32 + lid],       w1h = sW1H[(8 + j) * 32 + lid];
            uint2 w0l = sW1L[j * 32 + lid],       w1l = sW1L[(8 + j) * 32 + lid];
            mma_bf16(a1, eh[0][0], eh[0][1], eh[0][2], eh[0][3], w0h.x, w0h.y);
            mma_bf16(a1, eh[1][0], eh[1][1], eh[1][2], eh[1][3], w1h.x, w1h.y);
            mma_bf16(a1, el[0][0], el[0][1], el[0][2], el[0][3], w0h.x, w0h.y);
            mma_bf16(a1, el[1][0], el[1][1], el[1][2], el[1][3], w1h.x, w1h.y);
            mma_bf16(a1, eh[0][0], eh[0][1], eh[0][2], eh[0][3], w0l.x, w0l.y);
            mma_bf16(a1, eh[1][0], eh[1][1], eh[1][2], eh[1][3], w1l.x, w1l.y);
        }
        {
            int j = 2 * t + 1;
            uint2 w0h = sW1H[j * 32 + lid],       w1h = sW1H[(8 + j) * 32 + lid];
            uint2 w0l = sW1L[j * 32 + lid],       w1l = sW1L[(8 + j) * 32 + lid];
            mma_bf16(a1b, eh[0][0], eh[0][1], eh[0][2], eh[0][3], w0h.x, w0h.y);
            mma_bf16(a1b, eh[1][0], eh[1][1], eh[1][2], eh[1][3], w1h.x, w1h.y);
            mma_bf16(a1b, el[0][0], el[0][1], el[0][2], el[0][3], w0h.x, w0h.y);
            mma_bf16(a1b, el[1][0], el[1][1], el[1][2], el[1][3], w1h.x, w1h.y);
            mma_bf16(a1b, eh[0][0], eh[0][1], eh[0][2], eh[0][3], w0l.x, w0l.y);
            mma_bf16(a1b, eh[1][0], eh[1][1], eh[1][2], eh[1][3], w1l.x, w1l.y);
        }

        // ---- bias + ReLU + re-split: layer1 C-frag == layer2 A-frag (k-tile t) ----
        int col0 = 16 * t + 2 * q;
        float2 ba = *(const float2*)(sB1 + col0);
        float2 bb = *(const float2*)(sB1 + col0 + 8);
        float h0 = fmaxf(a1[0]  + ba.x, 0.0f), h1 = fmaxf(a1[1]  + ba.y, 0.0f);
        float h2 = fmaxf(a1[2]  + ba.x, 0.0f), h3 = fmaxf(a1[3]  + ba.y, 0.0f);
        float g0 = fmaxf(a1b[0] + bb.x, 0.0f), g1 = fmaxf(a1b[1] + bb.y, 0.0f);
        float g2 = fmaxf(a1b[2] + bb.x, 0.0f), g3 = fmaxf(a1b[3] + bb.y, 0.0f);
        uint32_t a0h = pack_hi(h0, h1), a1h_ = pack_hi(h2, h3);
        uint32_t a2h = pack_hi(g0, g1), a3h = pack_hi(g2, g3);
        uint32_t a0l = pack_lo(h0, h1, a0h), a1l = pack_lo(h2, h3, a1h_);
        uint32_t a2l = pack_lo(g0, g1, a2h), a3l = pack_lo(g2, g3, a3h);

        // ---- layer2: accumulate k-tile t into all 4 n-tiles (3-term split) ----
#pragma unroll
        for (int nt = 0; nt < 4; nt++) {
            uint2 bh = sW2H[(t * 4 + nt) * 32 + lid];
            uint2 bl = sW2L[(t * 4 + nt) * 32 + lid];
            mma_bf16(acc2[nt], a0h, a1h_, a2h, a3h, bh.x, bh.y);
            mma_bf16(acc2[nt], a0l, a1l,  a2l, a3l, bh.x, bh.y);
            mma_bf16(acc2[nt], a0h, a1h_, a2h, a3h, bl.x, bl.y);
        }
    }

    // Store D (pitch 36 floats) into aliased buffer.
    {
        int rA = r0 + (lid >> 2);
        int rB = rA + 8;
        int cb = 2 * q;
#pragma unroll
        for (int nt = 0; nt < 4; nt++) {
            int c = nt * 8 + cb;
            *(float2*)(sD + rA * DPITCH_F + c) = make_float2(acc2[nt][0], acc2[nt][1]);
            *(float2*)(sD + rB * DPITCH_F + c) = make_float2(acc2[nt][2], acc2[nt][3]);
        }
    }
    __syncthreads();

    // Epilogue: threads 0-127 -> probs; threads 128-255 -> edge_index passthrough.
    if (tid < EPB) {
        if (tid < nE) {
            float z = sB3;
            const float4* drow = (const float4*)(sD + tid * DPITCH_F);
#pragma unroll
            for (int p = 0; p < 8; p++) {
                float4 d = drow[p];
                z = fmaf(fmaxf(d.x + sB2[4 * p + 0], 0.0f), sW3[4 * p + 0], z);
                z = fmaf(fmaxf(d.y + sB2[4 * p + 1], 0.0f), sW3[4 * p + 1], z);
                z = fmaf(fmaxf(d.z + sB2[4 * p + 2], 0.0f), sW3[4 * p + 2], z);
                z = fmaf(fmaxf(d.w + sB2[4 * p + 3], 0.0f), sW3[4 * p + 3], z);
            }
            out[base + tid] = 1.0f / (1.0f + __expf(-z));
        }
    } else if (do_idx) {
        int t2 = tid - EPB;
        if (t2 < nE) {
            out[(size_t)E + base + t2]     = (float)sU[t2];
            out[(size_t)2 * E + base + t2] = (float)sV[t2];
        }
    }
}

extern "C" void kernel_launch(void* const* d_in, const int* in_sizes, int n_in,
                              void* d_out, int out_size) {
    const float* emb = (const float*)d_in[0];
    const int*   ei  = (const int*)d_in[1];
    const float* W1  = (const float*)d_in[2];
    const float* b1  = (const float*)d_in[3];
    const float* W2  = (const float*)d_in[4];
    const float* b2  = (const float*)d_in[5];
    const float* W3  = (const float*)d_in[6];
    const float* b3  = (const float*)d_in[7];

    int E      = in_sizes[1] / 2;
    float* out = (float*)d_out;
    int do_idx = (out_size >= 3 * E) ? 1 : 0;

    prep_frags<<<1, 256>>>(W1, W2);
    edge_kernel<<<(E + EPB - 1) / EPB, 256>>>(emb, ei, b1, b2, W3, b3, out, E, do_idx);
}

// round 11
// speedup vs baseline: 2.9296x; 1.0746x over previous
#include <cuda_runtime.h>
#include <cuda_bf16.h>
#include <cstdint>

// EdgeDecoder: probs = sigmoid(relu(relu(concat(emb[u],emb[v])@W1+b1)@W2+b2)@W3+b3)
// R10: fully fused tensor-core version (layer1 MMA -> in-register relu/resplit ->
//      layer2 MMA), 3-term bf16 hi/lo splits, raw-emb gather (128B/edge).
// R11: register epilogue — layer3 dot computed directly in C-fragment layout with
//      quad shfl_xor reduction. Removes D smem round-trip + 2 barriers (L1 was 86%).

#define EPB 128
#define APITCH 80        // A row pitch bytes (64B emb-pair data + 16 pad)

// Per-lane packed fragments (prep kernel): W1 [kt1(2)][j(8)][lane], W2 [kt(4)][nt(4)][lane]
__device__ __align__(16) uint2 g_W1fragHi[512];
__device__ __align__(16) uint2 g_W1fragLo[512];
__device__ __align__(16) uint2 g_W2fragHi[512];
__device__ __align__(16) uint2 g_W2fragLo[512];

__device__ __forceinline__ uint32_t smem_u32(const void* p) {
    uint32_t a;
    asm("{ .reg .u64 t; cvta.to.shared.u64 t, %1; cvt.u32.u64 %0, t; }" : "=r"(a) : "l"(p));
    return a;
}
__device__ __forceinline__ void ldmatrix_x4(uint32_t& a0, uint32_t& a1,
                                            uint32_t& a2, uint32_t& a3, uint32_t addr) {
    asm volatile("ldmatrix.sync.aligned.m8n8.x4.shared.b16 {%0,%1,%2,%3}, [%4];"
                 : "=r"(a0), "=r"(a1), "=r"(a2), "=r"(a3) : "r"(addr));
}
__device__ __forceinline__ void mma_bf16(float* c, uint32_t a0, uint32_t a1,
                                         uint32_t a2, uint32_t a3,
                                         uint32_t b0, uint32_t b1) {
    asm volatile("mma.sync.aligned.m16n8k16.row.col.f32.bf16.bf16.f32 "
                 "{%0,%1,%2,%3},{%4,%5,%6,%7},{%8,%9},{%0,%1,%2,%3};"
                 : "+f"(c[0]), "+f"(c[1]), "+f"(c[2]), "+f"(c[3])
                 : "r"(a0), "r"(a1), "r"(a2), "r"(a3), "r"(b0), "r"(b1));
}
__device__ __forceinline__ uint32_t pack_hi(float a, float b) {
    __nv_bfloat162 h = __floats2bfloat162_rn(a, b);
    return *(uint32_t*)&h;
}
__device__ __forceinline__ uint32_t pack_lo(float a, float b, uint32_t hi) {
    __nv_bfloat162 h = *(__nv_bfloat162*)&hi;
    __nv_bfloat162 l = __floats2bfloat162_rn(a - __bfloat162float(h.x),
                                             b - __bfloat162float(h.y));
    return *(uint32_t*)&l;
}

// ---------------- prep: per-lane packed W1/W2 fragments (hi/lo split) ----------------
__global__ void __launch_bounds__(256)
prep_frags(const float* __restrict__ W1, const float* __restrict__ W2) {
    int tid = threadIdx.x;
    for (int e = tid; e < 512; e += 256) {
        int lane = e & 31;
        {   // W1 [32 x 64]: e = kt1*256 + j*32 + lane
            int kt1 = e >> 8, j = (e >> 5) & 7;
            int k0 = kt1 * 16 + (lane & 3) * 2;
            int n  = j * 8 + (lane >> 2);
            float p00 = W1[(k0 + 0) * 64 + n], p01 = W1[(k0 + 1) * 64 + n];
            float p10 = W1[(k0 + 8) * 64 + n], p11 = W1[(k0 + 9) * 64 + n];
            uint32_t h0 = pack_hi(p00, p01), h1 = pack_hi(p10, p11);
            g_W1fragHi[e] = make_uint2(h0, h1);
            g_W1fragLo[e] = make_uint2(pack_lo(p00, p01, h0), pack_lo(p10, p11, h1));
        }
        {   // W2 [64 x 32]: e = kt*128 + nt*32 + lane
            int kt = e >> 7, nt = (e >> 5) & 3;
            int k0 = kt * 16 + (lane & 3) * 2;
            int n  = nt * 8 + (lane >> 2);
            float p00 = W2[(k0 + 0) * 32 + n], p01 = W2[(k0 + 1) * 32 + n];
            float p10 = W2[(k0 + 8) * 32 + n], p11 = W2[(k0 + 9) * 32 + n];
            uint32_t h0 = pack_hi(p00, p01), h1 = pack_hi(p10, p11);
            g_W2fragHi[e] = make_uint2(h0, h1);
            g_W2fragLo[e] = make_uint2(pack_lo(p00, p01, h0), pack_lo(p10, p11, h1));
        }
    }
}

// ---------------- fused edge kernel ----------------
__global__ void __launch_bounds__(256, 4)
edge_kernel(const float* __restrict__ emb,
            const int* __restrict__ ei,
            const float* __restrict__ b1,
            const float* __restrict__ b2,
            const float* __restrict__ W3,
            const float* __restrict__ b3,
            float* __restrict__ out,
            int E, int do_idx) {
    __shared__ __align__(16) unsigned char sAhi[EPB * APITCH];
    __shared__ __align__(16) unsigned char sAlo[EPB * APITCH];
    __shared__ __align__(16) uint2 sW1H[512], sW1L[512], sW2H[512], sW2L[512];
    __shared__ int sU[EPB], sV[EPB];
    __shared__ __align__(16) float sB1[64];
    __shared__ __align__(16) float sB2[32], sW3[32];
    __shared__ float sB3;

    const int tid = threadIdx.x;
    const int wid = tid >> 5, lid = tid & 31;
    const int q = lid & 3;

    for (int i = tid; i < 512; i += 256) {
        sW1H[i] = g_W1fragHi[i]; sW1L[i] = g_W1fragLo[i];
        sW2H[i] = g_W2fragHi[i]; sW2L[i] = g_W2fragLo[i];
    }
    if (tid < 64) sB1[tid] = b1[tid];
    if (tid < 32) { sB2[tid] = b2[tid]; sW3[tid] = W3[tid]; }
    if (tid == 0) sB3 = b3[0];

    const int base = blockIdx.x * EPB;
    const int nE = min(EPB, E - base);
    if (tid < EPB) {
        if (tid < nE) { sU[tid] = __ldg(ei + base + tid); sV[tid] = __ldg(ei + (size_t)E + base + tid); }
        else          { sU[tid] = 0; sV[tid] = 0; }
    }
    __syncthreads();

    // Gather raw embeddings: 4 lanes cover one node row (64B). Split to bf16 hi/lo.
#pragma unroll
    for (int i = 0; i < 4; i++) {
        int idx = i * 256 + tid;
        int le = idx >> 3;
        int which = (idx >> 2) & 1;
        int s = idx & 3;
        int node = which ? sV[le] : sU[le];
        float4 v = __ldg((const float4*)(emb + (size_t)node * 16) + s);
        uint32_t h01 = pack_hi(v.x, v.y), h23 = pack_hi(v.z, v.w);
        uint32_t l01 = pack_lo(v.x, v.y, h01), l23 = pack_lo(v.z, v.w, h23);
        uint32_t off = (uint32_t)le * APITCH + (uint32_t)which * 32 + (uint32_t)s * 8;
        *(uint2*)(sAhi + off) = make_uint2(h01, h23);
        *(uint2*)(sAlo + off) = make_uint2(l01, l23);
    }
    __syncthreads();

    // Load emb A fragments (2 k-tiles, hi+lo). Warp computes rows [wid*16, +16).
    const int r0 = wid * 16;
    const uint32_t abh = smem_u32(sAhi);
    const uint32_t abl = smem_u32(sAlo);
    const uint32_t rowoff = ((uint32_t)r0 + (uint32_t)(lid & 15)) * APITCH + ((uint32_t)(lid >> 4)) * 16;
    uint32_t eh[2][4], el[2][4];
    ldmatrix_x4(eh[0][0], eh[0][1], eh[0][2], eh[0][3], abh + rowoff);
    ldmatrix_x4(eh[1][0], eh[1][1], eh[1][2], eh[1][3], abh + rowoff + 32);
    ldmatrix_x4(el[0][0], el[0][1], el[0][2], el[0][3], abl + rowoff);
    ldmatrix_x4(el[1][0], el[1][1], el[1][2], el[1][3], abl + rowoff + 32);

    float acc2[4][4];
#pragma unroll
    for (int nt = 0; nt < 4; nt++)
#pragma unroll
        for (int r = 0; r < 4; r++) acc2[nt][r] = 0.0f;

#pragma unroll
    for (int t = 0; t < 4; t++) {
        // ---- layer1: n-tiles j = 2t, 2t+1 (K=32 over 2 k-tiles, 3-term split) ----
        float a1[4] = {0, 0, 0, 0}, a1b[4] = {0, 0, 0, 0};
        {
            int j = 2 * t;
            uint2 w0h = sW1H[j * 32 + lid],       w1h = sW1H[(8 + j) * 32 + lid];
            uint2 w0l = sW1L[j * 32 + lid],       w1l = sW1L[(8 + j) * 32 + lid];
            mma_bf16(a1, eh[0][0], eh[0][1], eh[0][2], eh[0][3], w0h.x, w0h.y);
            mma_bf16(a1, eh[1][0], eh[1][1], eh[1][2], eh[1][3], w1h.x, w1h.y);
            mma_bf16(a1, el[0][0], el[0][1], el[0][2], el[0][3], w0h.x, w0h.y);
            mma_bf16(a1, el[1][0], el[1][1], el[1][2], el[1][3], w1h.x, w1h.y);
            mma_bf16(a1, eh[0][0], eh[0][1], eh[0][2], eh[0][3], w0l.x, w0l.y);
            mma_bf16(a1, eh[1][0], eh[1][1], eh[1][2], eh[1][3], w1l.x, w1l.y);
        }
        {
            int j = 2 * t + 1;
            uint2 w0h = sW1H[j * 32 + lid],       w1h = sW1H[(8 + j) * 32 + lid];
            uint2 w0l = sW1L[j * 32 + lid],       w1l = sW1L[(8 + j) * 32 + lid];
            mma_bf16(a1b, eh[0][0], eh[0][1], eh[0][2], eh[0][3], w0h.x, w0h.y);
            mma_bf16(a1b, eh[1][0], eh[1][1], eh[1][2], eh[1][3], w1h.x, w1h.y);
            mma_bf16(a1b, el[0][0], el[0][1], el[0][2], el[0][3], w0h.x, w0h.y);
            mma_bf16(a1b, el[1][0], el[1][1], el[1][2], el[1][3], w1h.x, w1h.y);
            mma_bf16(a1b, eh[0][0], eh[0][1], eh[0][2], eh[0][3], w0l.x, w0l.y);
            mma_bf16(a1b, eh[1][0], eh[1][1], eh[1][2], eh[1][3], w1l.x, w1l.y);
        }

        // ---- bias + ReLU + re-split: layer1 C-frag == layer2 A-frag (k-tile t) ----
        int col0 = 16 * t + 2 * q;
        float2 ba = *(const float2*)(sB1 + col0);
        float2 bb = *(const float2*)(sB1 + col0 + 8);
        float h0 = fmaxf(a1[0]  + ba.x, 0.0f), h1 = fmaxf(a1[1]  + ba.y, 0.0f);
        float h2 = fmaxf(a1[2]  + ba.x, 0.0f), h3 = fmaxf(a1[3]  + ba.y, 0.0f);
        float g0 = fmaxf(a1b[0] + bb.x, 0.0f), g1 = fmaxf(a1b[1] + bb.y, 0.0f);
        float g2 = fmaxf(a1b[2] + bb.x, 0.0f), g3 = fmaxf(a1b[3] + bb.y, 0.0f);
        uint32_t a0h = pack_hi(h0, h1), a1h_ = pack_hi(h2, h3);
        uint32_t a2h = pack_hi(g0, g1), a3h = pack_hi(g2, g3);
        uint32_t a0l = pack_lo(h0, h1, a0h), a1l = pack_lo(h2, h3, a1h_);
        uint32_t a2l = pack_lo(g0, g1, a2h), a3l = pack_lo(g2, g3, a3h);

        // ---- layer2: accumulate k-tile t into all 4 n-tiles (3-term split) ----
#pragma unroll
        for (int nt = 0; nt < 4; nt++) {
            uint2 bh = sW2H[(t * 4 + nt) * 32 + lid];
            uint2 bl = sW2L[(t * 4 + nt) * 32 + lid];
            mma_bf16(acc2[nt], a0h, a1h_, a2h, a3h, bh.x, bh.y);
            mma_bf16(acc2[nt], a0l, a1l,  a2l, a3l, bh.x, bh.y);
            mma_bf16(acc2[nt], a0h, a1h_, a2h, a3h, bl.x, bl.y);
        }
    }

    // ---- register epilogue: layer3 dot in C-fragment layout + quad reduction ----
    // Lane owns cols {nt*8+2q, nt*8+2q+1} of rows rA=r0+(lid>>2) and rB=rA+8.
    float zA = 0.0f, zB = 0.0f;
#pragma unroll
    for (int nt = 0; nt < 4; nt++) {
        float2 bb = *(const float2*)(sB2 + nt * 8 + 2 * q);
        float2 ww = *(const float2*)(sW3 + nt * 8 + 2 * q);
        zA = fmaf(fmaxf(acc2[nt][0] + bb.x, 0.0f), ww.x, zA);
        zA = fmaf(fmaxf(acc2[nt][1] + bb.y, 0.0f), ww.y, zA);
        zB = fmaf(fmaxf(acc2[nt][2] + bb.x, 0.0f), ww.x, zB);
        zB = fmaf(fmaxf(acc2[nt][3] + bb.y, 0.0f), ww.y, zB);
    }
    zA += __shfl_xor_sync(0xffffffffu, zA, 1);
    zA += __shfl_xor_sync(0xffffffffu, zA, 2);
    zB += __shfl_xor_sync(0xffffffffu, zB, 1);
    zB += __shfl_xor_sync(0xffffffffu, zB, 2);
    if (q == 0) {
        int rA = r0 + (lid >> 2);
        int rB = rA + 8;
        if (rA < nE) out[base + rA] = 1.0f / (1.0f + __expf(-(zA + sB3)));
        if (rB < nE) out[base + rB] = 1.0f / (1.0f + __expf(-(zB + sB3)));
    }

    // ---- edge_index passthrough (coalesced, from staged indices) ----
    if (do_idx) {
        if (tid < EPB) {
            if (tid < nE) out[(size_t)E + base + tid] = (float)sU[tid];
        } else {
            int t2 = tid - EPB;
            if (t2 < nE) out[(size_t)2 * E + base + t2] = (float)sV[t2];
        }
    }
}

extern "C" void kernel_launch(void* const* d_in, const int* in_sizes, int n_in,
                              void* d_out, int out_size) {
    const float* emb = (const float*)d_in[0];
    const int*   ei  = (const int*)d_in[1];
    const float* W1  = (const float*)d_in[2];
    const float* b1  = (const float*)d_in[3];
    const float* W2  = (const float*)d_in[4];
    const float* b2  = (const float*)d_in[5];
    const float* W3  = (const float*)d_in[6];
    const float* b3  = (const float*)d_in[7];

    int E      = in_sizes[1] / 2;
    float* out = (float*)d_out;
    int do_idx = (out_size >= 3 * E) ? 1 : 0;

    prep_frags<<<1, 256>>>(W1, W2);
    edge_kernel<<<(E + EPB - 1) / EPB, 256>>>(emb, ei, b1, b2, W3, b3, out, E, do_idx);
}

// round 12
// speedup vs baseline: 2.9419x; 1.0042x over previous
#include <cuda_runtime.h>
#include <cuda_bf16.h>
#include <cstdint>

// EdgeDecoder: probs = sigmoid(relu(relu(concat(emb[u],emb[v])@W1+b1)@W2+b2)@W3+b3)
// R10: fully fused tensor-core version (layer1 MMA -> in-register relu/resplit ->
//      layer2 MMA), 3-term bf16 hi/lo splits, raw-emb gather (128B/edge).
// R11: register epilogue — layer3 dot computed directly in C-fragment layout with
//      quad shfl_xor reduction. Removes D smem round-trip + 2 barriers (L1 was 86%).

#define EPB 128
#define APITCH 80        // A row pitch bytes (64B emb-pair data + 16 pad)

// Per-lane packed fragments (prep kernel): W1 [kt1(2)][j(8)][lane], W2 [kt(4)][nt(4)][lane]
__device__ __align__(16) uint2 g_W1fragHi[512];
__device__ __align__(16) uint2 g_W1fragLo[512];
__device__ __align__(16) uint2 g_W2fragHi[512];
__device__ __align__(16) uint2 g_W2fragLo[512];

__device__ __forceinline__ uint32_t smem_u32(const void* p) {
    uint32_t a;
    asm("{ .reg .u64 t; cvta.to.shared.u64 t, %1; cvt.u32.u64 %0, t; }" : "=r"(a) : "l"(p));
    return a;
}
__device__ __forceinline__ void ldmatrix_x4(uint32_t& a0, uint32_t& a1,
                                            uint32_t& a2, uint32_t& a3, uint32_t addr) {
    asm volatile("ldmatrix.sync.aligned.m8n8.x4.shared.b16 {%0,%1,%2,%3}, [%4];"
                 : "=r"(a0), "=r"(a1), "=r"(a2), "=r"(a3) : "r"(addr));
}
__device__ __forceinline__ void mma_bf16(float* c, uint32_t a0, uint32_t a1,
                                         uint32_t a2, uint32_t a3,
                                         uint32_t b0, uint32_t b1) {
    asm volatile("mma.sync.aligned.m16n8k16.row.col.f32.bf16.bf16.f32 "
                 "{%0,%1,%2,%3},{%4,%5,%6,%7},{%8,%9},{%0,%1,%2,%3};"
                 : "+f"(c[0]), "+f"(c[1]), "+f"(c[2]), "+f"(c[3])
                 : "r"(a0), "r"(a1), "r"(a2), "r"(a3), "r"(b0), "r"(b1));
}
__device__ __forceinline__ uint32_t pack_hi(float a, float b) {
    __nv_bfloat162 h = __floats2bfloat162_rn(a, b);
    return *(uint32_t*)&h;
}
__device__ __forceinline__ uint32_t pack_lo(float a, float b, uint32_t hi) {
    __nv_bfloat162 h = *(__nv_bfloat162*)&hi;
    __nv_bfloat162 l = __floats2bfloat162_rn(a - __bfloat162float(h.x),
                                             b - __bfloat162float(h.y));
    return *(uint32_t*)&l;
}

// ---------------- prep: per-lane packed W1/W2 fragments (hi/lo split) ----------------
__global__ void __launch_bounds__(256)
prep_frags(const float* __restrict__ W1, const float* __restrict__ W2) {
    int tid = threadIdx.x;
    for (int e = tid; e < 512; e += 256) {
        int lane = e & 31;
        {   // W1 [32 x 64]: e = kt1*256 + j*32 + lane
            int kt1 = e >> 8, j = (e >> 5) & 7;
            int k0 = kt1 * 16 + (lane & 3) * 2;
            int n  = j * 8 + (lane >> 2);
            float p00 = W1[(k0 + 0) * 64 + n], p01 = W1[(k0 + 1) * 64 + n];
            float p10 = W1[(k0 + 8) * 64 + n], p11 = W1[(k0 + 9) * 64 + n];
            uint32_t h0 = pack_hi(p00, p01), h1 = pack_hi(p10, p11);
            g_W1fragHi[e] = make_uint2(h0, h1);
            g_W1fragLo[e] = make_uint2(pack_lo(p00, p01, h0), pack_lo(p10, p11, h1));
        }
        {   // W2 [64 x 32]: e = kt*128 + nt*32 + lane
            int kt = e >> 7, nt = (e >> 5) & 3;
            int k0 = kt * 16 + (lane & 3) * 2;
            int n  = nt * 8 + (lane >> 2);
            float p00 = W2[(k0 + 0) * 32 + n], p01 = W2[(k0 + 1) * 32 + n];
            float p10 = W2[(k0 + 8) * 32 + n], p11 = W2[(k0 + 9) * 32 + n];
            uint32_t h0 = pack_hi(p00, p01), h1 = pack_hi(p10, p11);
            g_W2fragHi[e] = make_uint2(h0, h1);
            g_W2fragLo[e] = make_uint2(pack_lo(p00, p01, h0), pack_lo(p10, p11, h1));
        }
    }
}

// ---------------- fused edge kernel ----------------
__global__ void __launch_bounds__(256, 4)
edge_kernel(const float* __restrict__ emb,
            const int* __restrict__ ei,
            const float* __restrict__ b1,
            const float* __restrict__ b2,
            const float* __restrict__ W3,
            const float* __restrict__ b3,
            float* __restrict__ out,
            int E, int do_idx) {
    __shared__ __align__(16) unsigned char sAhi[EPB * APITCH];
    __shared__ __align__(16) unsigned char sAlo[EPB * APITCH];
    __shared__ __align__(16) uint2 sW1H[512], sW1L[512], sW2H[512], sW2L[512];
    __shared__ int sU[EPB], sV[EPB];
    __shared__ __align__(16) float sB1[64];
    __shared__ __align__(16) float sB2[32], sW3[32];
    __shared__ float sB3;

    const int tid = threadIdx.x;
    const int wid = tid >> 5, lid = tid & 31;
    const int q = lid & 3;

    for (int i = tid; i < 512; i += 256) {
        sW1H[i] = g_W1fragHi[i]; sW1L[i] = g_W1fragLo[i];
        sW2H[i] = g_W2fragHi[i]; sW2L[i] = g_W2fragLo[i];
    }
    if (tid < 64) sB1[tid] = b1[tid];
    if (tid < 32) { sB2[tid] = b2[tid]; sW3[tid] = W3[tid]; }
    if (tid == 0) sB3 = b3[0];

    const int base = blockIdx.x * EPB;
    const int nE = min(EPB, E - base);
    if (tid < EPB) {
        if (tid < nE) { sU[tid] = __ldg(ei + base + tid); sV[tid] = __ldg(ei + (size_t)E + base + tid); }
        else          { sU[tid] = 0; sV[tid] = 0; }
    }
    __syncthreads();

    // Gather raw embeddings: 4 lanes cover one node row (64B). Split to bf16 hi/lo.
#pragma unroll
    for (int i = 0; i < 4; i++) {
        int idx = i * 256 + tid;
        int le = idx >> 3;
        int which = (idx >> 2) & 1;
        int s = idx & 3;
        int node = which ? sV[le] : sU[le];
        float4 v = __ldg((const float4*)(emb + (size_t)node * 16) + s);
        uint32_t h01 = pack_hi(v.x, v.y), h23 = pack_hi(v.z, v.w);
        uint32_t l01 = pack_lo(v.x, v.y, h01), l23 = pack_lo(v.z, v.w, h23);
        uint32_t off = (uint32_t)le * APITCH + (uint32_t)which * 32 + (uint32_t)s * 8;
        *(uint2*)(sAhi + off) = make_uint2(h01, h23);
        *(uint2*)(sAlo + off) = make_uint2(l01, l23);
    }
    __syncthreads();

    // Load emb A fragments (2 k-tiles, hi+lo). Warp computes rows [wid*16, +16).
    const int r0 = wid * 16;
    const uint32_t abh = smem_u32(sAhi);
    const uint32_t abl = smem_u32(sAlo);
    const uint32_t rowoff = ((uint32_t)r0 + (uint32_t)(lid & 15)) * APITCH + ((uint32_t)(lid >> 4)) * 16;
    uint32_t eh[2][4], el[2][4];
    ldmatrix_x4(eh[0][0], eh[0][1], eh[0][2], eh[0][3], abh + rowoff);
    ldmatrix_x4(eh[1][0], eh[1][1], eh[1][2], eh[1][3], abh + rowoff + 32);
    ldmatrix_x4(el[0][0], el[0][1], el[0][2], el[0][3], abl + rowoff);
    ldmatrix_x4(el[1][0], el[1][1], el[1][2], el[1][3], abl + rowoff + 32);

    float acc2[4][4];
#pragma unroll
    for (int nt = 0; nt < 4; nt++)
#pragma unroll
        for (int r = 0; r < 4; r++) acc2[nt][r] = 0.0f;

#pragma unroll
    for (int t = 0; t < 4; t++) {
        // ---- layer1: n-tiles j = 2t, 2t+1 (K=32 over 2 k-tiles, 3-term split) ----
        float a1[4] = {0, 0, 0, 0}, a1b[4] = {0, 0, 0, 0};
        {
            int j = 2 * t;
            uint2 w0h = sW1H[j * 32 + lid],       w1h = sW1H[(8 + j) * 32 + lid];
            uint2 w0l = sW1L[j * 32 + lid],       w1l = sW1L[(8 + j) * 32 + lid];
            mma_bf16(a1, eh[0][0], eh[0][1], eh[0][2], eh[0][3], w0h.x, w0h.y);
            mma_bf16(a1, eh[1][0], eh[1][1], eh[1][2], eh[1][3], w1h.x, w1h.y);
            mma_bf16(a1, el[0][0], el[0][1], el[0][2], el[0][3], w0h.x, w0h.y);
            mma_bf16(a1, el[1][0], el[1][1], el[1][2], el[1][3], w1h.x, w1h.y);
            mma_bf16(a1, eh[0][0], eh[0][1], eh[0][2], eh[0][3], w0l.x, w0l.y);
            mma_bf16(a1, eh[1][0], eh[1][1], eh[1][2], eh[1][3], w1l.x, w1l.y);
        }
        {
            int j = 2 * t + 1;
            uint2 w0h = sW1H[j * 32 + lid],       w1h = sW1H[(8 + j) * 32 + lid];
            uint2 w0l = sW1L[j * 32 + lid],       w1l = sW1L[(8 + j) * 32 + lid];
            mma_bf16(a1b, eh[0][0], eh[0][1], eh[0][2], eh[0][3], w0h.x, w0h.y);
            mma_bf16(a1b, eh[1][0], eh[1][1], eh[1][2], eh[1][3], w1h.x, w1h.y);
            mma_bf16(a1b, el[0][0], el[0][1], el[0][2], el[0][3], w0h.x, w0h.y);
            mma_bf16(a1b, el[1][0], el[1][1], el[1][2], el[1][3], w1h.x, w1h.y);
            mma_bf16(a1b, eh[0][0], eh[0][1], eh[0][2], eh[0][3], w0l.x, w0l.y);
            mma_bf16(a1b, eh[1][0], eh[1][1], eh[1][2], eh[1][3], w1l.x, w1l.y);
        }

        // ---- bias + ReLU + re-split: layer1 C-frag == layer2 A-frag (k-tile t) ----
        int col0 = 16 * t + 2 * q;
        float2 ba = *(const float2*)(sB1 + col0);
        float2 bb = *(const float2*)(sB1 + col0 + 8);
        float h0 = fmaxf(a1[0]  + ba.x, 0.0f), h1 = fmaxf(a1[1]  + ba.y, 0.0f);
        float h2 = fmaxf(a1[2]  + ba.x, 0.0f), h3 = fmaxf(a1[3]  + ba.y, 0.0f);
        float g0 = fmaxf(a1b[0] + bb.x, 0.0f), g1 = fmaxf(a1b[1] + bb.y, 0.0f);
        float g2 = fmaxf(a1b[2] + bb.x, 0.0f), g3 = fmaxf(a1b[3] + bb.y, 0.0f);
        uint32_t a0h = pack_hi(h0, h1), a1h_ = pack_hi(h2, h3);
        uint32_t a2h = pack_hi(g0, g1), a3h = pack_hi(g2, g3);
        uint32_t a0l = pack_lo(h0, h1, a0h), a1l = pack_lo(h2, h3, a1h_);
        uint32_t a2l = pack_lo(g0, g1, a2h), a3l = pack_lo(g2, g3, a3h);

        // ---- layer2: accumulate k-tile t into all 4 n-tiles (3-term split) ----
#pragma unroll
        for (int nt = 0; nt < 4; nt++) {
            uint2 bh = sW2H[(t * 4 + nt) * 32 + lid];
            uint2 bl = sW2L[(t * 4 + nt) * 32 + lid];
            mma_bf16(acc2[nt], a0h, a1h_, a2h, a3h, bh.x, bh.y);
            mma_bf16(acc2[nt], a0l, a1l,  a2l, a3l, bh.x, bh.y);
            mma_bf16(acc2[nt], a0h, a1h_, a2h, a3h, bl.x, bl.y);
        }
    }

    // ---- register epilogue: layer3 dot in C-fragment layout + quad reduction ----
    // Lane owns cols {nt*8+2q, nt*8+2q+1} of rows rA=r0+(lid>>2) and rB=rA+8.
    float zA = 0.0f, zB = 0.0f;
#pragma unroll
    for (int nt = 0; nt < 4; nt++) {
        float2 bb = *(const float2*)(sB2 + nt * 8 + 2 * q);
        float2 ww = *(const float2*)(sW3 + nt * 8 + 2 * q);
        zA = fmaf(fmaxf(acc2[nt][0] + bb.x, 0.0f), ww.x, zA);
        zA = fmaf(fmaxf(acc2[nt][1] + bb.y, 0.0f), ww.y, zA);
        zB = fmaf(fmaxf(acc2[nt][2] + bb.x, 0.0f), ww.x, zB);
        zB = fmaf(fmaxf(acc2[nt][3] + bb.y, 0.0f), ww.y, zB);
    }
    zA += __shfl_xor_sync(0xffffffffu, zA, 1);
    zA += __shfl_xor_sync(0xffffffffu, zA, 2);
    zB += __shfl_xor_sync(0xffffffffu, zB, 1);
    zB += __shfl_xor_sync(0xffffffffu, zB, 2);
    if (q == 0) {
        int rA = r0 + (lid >> 2);
        int rB = rA + 8;
        if (rA < nE) out[base + rA] = 1.0f / (1.0f + __expf(-(zA + sB3)));
        if (rB < nE) out[base + rB] = 1.0f / (1.0f + __expf(-(zB + sB3)));
    }

    // ---- edge_index passthrough (coalesced, from staged indices) ----
    if (do_idx) {
        if (tid < EPB) {
            if (tid < nE) out[(size_t)E + base + tid] = (float)sU[tid];
        } else {
            int t2 = tid - EPB;
            if (t2 < nE) out[(size_t)2 * E + base + t2] = (float)sV[t2];
        }
    }
}

extern "C" void kernel_launch(void* const* d_in, const int* in_sizes, int n_in,
                              void* d_out, int out_size) {
    const float* emb = (const float*)d_in[0];
    const int*   ei  = (const int*)d_in[1];
    const float* W1  = (const float*)d_in[2];
    const float* b1  = (const float*)d_in[3];
    const float* W2  = (const float*)d_in[4];
    const float* b2  = (const float*)d_in[5];
    const float* W3  = (const float*)d_in[6];
    const float* b3  = (const float*)d_in[7];

    int E      = in_sizes[1] / 2;
    float* out = (float*)d_out;
    int do_idx = (out_size >= 3 * E) ? 1 : 0;

    prep_frags<<<1, 256>>>(W1, W2);
    edge_kernel<<<(E + EPB - 1) / EPB, 256>>>(emb, ei, b1, b2, W3, b3, out, E, do_idx);
}